// round 1
// baseline (speedup 1.0000x reference)
#include <cuda_runtime.h>
#include <math.h>

// Problem constants
#define E_ 400000
#define NN_ 50000
#define B_ 50
#define D_ 64
#define GATES 256

// scratch (device globals: no allocation allowed)
__device__ float g_mail[NN_ * D_];
__device__ float g_ecomb[B_ * D_];
__device__ float g_ncomb[B_ * D_];

__device__ __forceinline__ float sigmoidf_(float x) {
    return 1.0f / (1.0f + expf(-x));
}

__device__ __forceinline__ unsigned long long pack2(float lo, float hi) {
    unsigned long long r;
    asm("mov.b64 %0, {%1, %2};" : "=l"(r) : "f"(lo), "f"(hi));
    return r;
}
__device__ __forceinline__ void unpack2(unsigned long long v, float& lo, float& hi) {
    asm("mov.b64 {%0, %1}, %2;" : "=f"(lo), "=f"(hi) : "l"(v));
}
// packed f32x2 FMA (B300 FFMA2 path — only reachable via PTX)
__device__ __forceinline__ void fma2(unsigned long long& acc, unsigned long long a, unsigned long long b) {
    asm("fma.rn.f32x2 %0, %1, %2, %0;" : "+l"(acc) : "l"(a), "l"(b));
}

// GEMM inner chunk: acc[m-pair][gate] += Xs[k][m-pair] * W[g][k]
// W read directly from global (L2-resident), Xs from smem (broadcast loads).
__device__ __forceinline__ void gemm_chunk(
    const float* __restrict__ W, int ldw, int rowA, int rowB,
    const float* __restrict__ Xs, int tyo, int k0, int klen,
    unsigned long long (&acc)[4][8])
{
    #pragma unroll 2
    for (int k4 = 0; k4 < klen; k4 += 4) {
        unsigned long long xm[4][4];
        #pragma unroll
        for (int kk = 0; kk < 4; ++kk) {
            const float* xr = Xs + (size_t)(k0 + k4 + kk) * 64 + tyo;
            ulonglong2 a = *(const ulonglong2*)xr;        // 16B-aligned, warp-broadcast
            ulonglong2 b = *(const ulonglong2*)(xr + 4);
            xm[kk][0] = a.x; xm[kk][1] = a.y; xm[kk][2] = b.x; xm[kk][3] = b.y;
        }
        #pragma unroll
        for (int j = 0; j < 8; ++j) {
            int g = (j < 4) ? (rowA + j) : (rowB + (j - 4));
            float4 w = *(const float4*)&W[(size_t)g * ldw + k4];
            float wv0 = w.x, wv1 = w.y, wv2 = w.z, wv3 = w.w;
            unsigned long long w2;
            w2 = pack2(wv0, wv0);
            #pragma unroll
            for (int i = 0; i < 4; ++i) fma2(acc[i][j], xm[0][i], w2);
            w2 = pack2(wv1, wv1);
            #pragma unroll
            for (int i = 0; i < 4; ++i) fma2(acc[i][j], xm[1][i], w2);
            w2 = pack2(wv2, wv2);
            #pragma unroll
            for (int i = 0; i < 4; ++i) fma2(acc[i][j], xm[2][i], w2);
            w2 = pack2(wv3, wv3);
            #pragma unroll
            for (int i = 0; i < 4; ++i) fma2(acc[i][j], xm[3][i], w2);
        }
    }
}

// MODE 0: edge LSTM  (K=320: [edge_feat | nf[src] | nf[dst] | g_repr[eg] | edge_h])
// MODE 1: node LSTM  (K=256: [node_feat | mail | g_repr[ng] | node_h])
template <int MODE>
__global__ void __launch_bounds__(256, 2)
lstm_gemm_kernel(
    const float* __restrict__ feat,     // edge_feat / node_feat
    const float* __restrict__ nfeat,    // node_feat (edge mode); unused node mode (uses g_mail)
    const float* __restrict__ grepr,
    const float* __restrict__ h_in,
    const float* __restrict__ c_in,
    const float* __restrict__ Wih,
    const float* __restrict__ Whh,
    const float* __restrict__ bih,
    const float* __restrict__ bhh,
    const int* __restrict__ src,
    const int* __restrict__ dst,
    const int* __restrict__ rgraph,
    float* __restrict__ out_r,
    float* __restrict__ out_h,
    float* __restrict__ out_c,
    int Mrows)
{
    constexpr int KTOT = (MODE == 0) ? 320 : 256;
    constexpr int KIH  = (MODE == 0) ? 256 : 192;
    constexpr int BM = 64;

    extern __shared__ float sm[];
    float* Xs = sm;                     // [KTOT][64] transposed X tile
    float* rsum = sm + KTOT * 64;      // [2][64] per-graph reduction
    float* gates_s = sm;               // reuse Xs after GEMM: [64][256]

    const int tid = threadIdx.x;
    const int tx = tid & 31;
    const int ty = tid >> 5;
    const int m0 = blockIdx.x * BM;
    const float* nf = (MODE == 0) ? nfeat : (const float*)g_mail;
    float* combp = (MODE == 0) ? g_ecomb : g_ncomb;

    // ---- gather X into smem, transposed: Xs[k][m] ----
    // m = tid&63 -> conflict-free smem column writes
    for (int idx = tid; idx < BM * (KTOT / 4); idx += 256) {
        int m = idx & 63;
        int c4 = (idx >> 6) * 4;
        int row = m0 + m;
        float4 v = make_float4(0.f, 0.f, 0.f, 0.f);
        if (row < Mrows) {
            if (MODE == 0) {
                if (c4 < 64)        v = *(const float4*)&feat[(size_t)row * 64 + c4];
                else if (c4 < 128)  v = *(const float4*)&nf[(size_t)src[row] * 64 + (c4 - 64)];
                else if (c4 < 192)  v = *(const float4*)&nf[(size_t)dst[row] * 64 + (c4 - 128)];
                else if (c4 < 256)  v = *(const float4*)&grepr[(size_t)rgraph[row] * 64 + (c4 - 192)];
                else                v = *(const float4*)&h_in[(size_t)row * 64 + (c4 - 256)];
            } else {
                if (c4 < 64)        v = *(const float4*)&feat[(size_t)row * 64 + c4];
                else if (c4 < 128)  v = *(const float4*)&nf[(size_t)row * 64 + (c4 - 64)];
                else if (c4 < 192)  v = *(const float4*)&grepr[(size_t)rgraph[row] * 64 + (c4 - 128)];
                else                v = *(const float4*)&h_in[(size_t)row * 64 + (c4 - 192)];
            }
        }
        Xs[(size_t)(c4 + 0) * 64 + m] = v.x;
        Xs[(size_t)(c4 + 1) * 64 + m] = v.y;
        Xs[(size_t)(c4 + 2) * 64 + m] = v.z;
        Xs[(size_t)(c4 + 3) * 64 + m] = v.w;
    }

    unsigned long long acc[4][8];
    #pragma unroll
    for (int i = 0; i < 4; ++i)
        #pragma unroll
        for (int j = 0; j < 8; ++j) acc[i][j] = 0ull;

    __syncthreads();

    const int rowA = tx * 4;          // gates [tx*4, tx*4+4)
    const int rowB = 128 + tx * 4;    // gates [128+tx*4, ...)
    const int tyo = ty * 8;

    gemm_chunk(Wih, KIH, rowA, rowB, Xs, tyo, 0, KIH, acc);
    gemm_chunk(Whh, 64,  rowA, rowB, Xs, tyo, KIH, 64, acc);

    __syncthreads();  // done reading Xs

    // unpack accumulators into gates smem: gates_s[m][g]
    #pragma unroll
    for (int i = 0; i < 4; ++i) {
        int m = ty * 8 + i * 2;
        #pragma unroll
        for (int j = 0; j < 8; ++j) {
            int g = (j < 4) ? (rowA + j) : (rowB + (j - 4));
            float lo, hi;
            unpack2(acc[i][j], lo, hi);
            gates_s[(size_t)m * 256 + g] = lo;
            gates_s[(size_t)(m + 1) * 256 + g] = hi;
        }
    }
    if (tid < 128) rsum[tid] = 0.f;
    __syncthreads();

    // ---- fused LSTM pointwise + scatter ----
    const int d = tid & 63;
    const float bi = bih[d] + bhh[d];
    const float bf = bih[64 + d] + bhh[64 + d];
    const float bg = bih[128 + d] + bhh[128 + d];
    const float bo = bih[192 + d] + bhh[192 + d];
    const int gfirst = rgraph[m0];
    const int mlast = (m0 + BM - 1 < Mrows) ? (m0 + BM - 1) : (Mrows - 1);
    const int glast = rgraph[mlast];

    float acc0 = 0.f, acc1 = 0.f;
    #pragma unroll 4
    for (int it = 0; it < 16; ++it) {
        int ml = it * 4 + (tid >> 6);
        int row = m0 + ml;
        if (row < Mrows) {
            float gi = gates_s[(size_t)ml * 256 + d] + bi;
            float gf = gates_s[(size_t)ml * 256 + 64 + d] + bf;
            float gg = gates_s[(size_t)ml * 256 + 128 + d] + bg;
            float go = gates_s[(size_t)ml * 256 + 192 + d] + bo;
            float c2 = sigmoidf_(gf) * c_in[(size_t)row * 64 + d] + sigmoidf_(gi) * tanhf(gg);
            float h = sigmoidf_(go) * tanhf(c2);
            float r = fmaxf(h, 0.f);
            out_r[(size_t)row * 64 + d] = r;
            out_h[(size_t)row * 64 + d] = h;
            out_c[(size_t)row * 64 + d] = c2;
            if (MODE == 0) {
                // mailbox: warp = one dst row, lanes = consecutive d -> coalesced REDG
                atomicAdd(&g_mail[(size_t)dst[row] * 64 + d], r);
            }
            int gr = rgraph[row];
            if (gr == gfirst) acc0 += r; else acc1 += r;
        }
    }
    atomicAdd(&rsum[d], acc0);
    atomicAdd(&rsum[64 + d], acc1);
    __syncthreads();
    if (tid < 64) {
        atomicAdd(&combp[(size_t)gfirst * 64 + tid], rsum[tid]);
    } else if (tid < 128 && glast != gfirst) {
        atomicAdd(&combp[(size_t)glast * 64 + (tid - 64)], rsum[tid]);
    }
}

// graph-level LSTM: B=50 graphs, one block each
__global__ void graph_lstm_kernel(
    const float* __restrict__ grepr,
    const float* __restrict__ h_in,
    const float* __restrict__ c_in,
    const float* __restrict__ Wih,
    const float* __restrict__ Whh,
    const float* __restrict__ bih,
    const float* __restrict__ bhh,
    float* __restrict__ out_r,
    float* __restrict__ out_h,
    float* __restrict__ out_c)
{
    __shared__ float xu[192];
    __shared__ float hu[64];
    __shared__ float gs[256];
    const int b = blockIdx.x;
    const int tid = threadIdx.x;

    if (tid < 64)       xu[tid] = g_ncomb[b * 64 + tid];
    else if (tid < 128) xu[tid] = g_ecomb[b * 64 + (tid - 64)];
    else if (tid < 192) xu[tid] = grepr[b * 64 + (tid - 128)];
    else                hu[tid - 192] = h_in[b * 64 + (tid - 192)];
    __syncthreads();

    float a = bih[tid] + bhh[tid];
    #pragma unroll 8
    for (int k = 0; k < 192; ++k) a += xu[k] * Wih[(size_t)tid * 192 + k];
    #pragma unroll 8
    for (int k = 0; k < 64; ++k)  a += hu[k] * Whh[(size_t)tid * 64 + k];
    gs[tid] = a;
    __syncthreads();

    if (tid < 64) {
        int dd = tid;
        float gi = gs[dd], gf = gs[64 + dd], gg = gs[128 + dd], go = gs[192 + dd];
        float c2 = sigmoidf_(gf) * c_in[b * 64 + dd] + sigmoidf_(gi) * tanhf(gg);
        float h = sigmoidf_(go) * tanhf(c2);
        out_r[b * 64 + dd] = fmaxf(h, 0.f);
        out_h[b * 64 + dd] = h;
        out_c[b * 64 + dd] = c2;
    }
}

__global__ void zero_scratch_kernel()
{
    int i = blockIdx.x * 256 + threadIdx.x;
    if (i < NN_ * D_) g_mail[i] = 0.f;
    if (i < B_ * D_) { g_ecomb[i] = 0.f; g_ncomb[i] = 0.f; }
}

extern "C" void kernel_launch(void* const* d_in, const int* in_sizes, int n_in,
                              void* d_out, int out_size)
{
    const float* edge_feat  = (const float*)d_in[0];
    const float* node_feat  = (const float*)d_in[1];
    const float* g_repr     = (const float*)d_in[2];
    const float* edge_h     = (const float*)d_in[3];
    const float* edge_c     = (const float*)d_in[4];
    const float* node_h     = (const float*)d_in[5];
    const float* node_c     = (const float*)d_in[6];
    const float* graph_h    = (const float*)d_in[7];
    const float* graph_c    = (const float*)d_in[8];
    const float* Wih_e      = (const float*)d_in[9];
    const float* Whh_e      = (const float*)d_in[10];
    const float* bih_e      = (const float*)d_in[11];
    const float* bhh_e      = (const float*)d_in[12];
    const float* Wih_n      = (const float*)d_in[13];
    const float* Whh_n      = (const float*)d_in[14];
    const float* bih_n      = (const float*)d_in[15];
    const float* bhh_n      = (const float*)d_in[16];
    const float* Wih_u      = (const float*)d_in[17];
    const float* Whh_u      = (const float*)d_in[18];
    const float* bih_u      = (const float*)d_in[19];
    const float* bhh_u      = (const float*)d_in[20];
    const int*   src        = (const int*)d_in[21];
    const int*   dst        = (const int*)d_in[22];
    const int*   edge_graph = (const int*)d_in[23];
    const int*   node_graph = (const int*)d_in[24];

    float* out = (float*)d_out;
    const size_t ED = (size_t)E_ * D_;
    const size_t ND = (size_t)NN_ * D_;
    const size_t BD = (size_t)B_ * D_;
    float* e_out = out;
    float* h_e   = out + ED;
    float* c_e   = out + 2 * ED;
    float* n_out = out + 3 * ED;
    float* h_n   = n_out + ND;
    float* c_n   = n_out + 2 * ND;
    float* u_out = n_out + 3 * ND;
    float* h_u   = u_out + BD;
    float* c_u   = u_out + 2 * BD;

    const int SMEM0 = (320 * 64 + 128) * 4;  // 82432 B (edge)
    const int SMEM1 = (256 * 64 + 128) * 4;  // 66048 B (node)
    cudaFuncSetAttribute(lstm_gemm_kernel<0>, cudaFuncAttributeMaxDynamicSharedMemorySize, SMEM0);
    cudaFuncSetAttribute(lstm_gemm_kernel<1>, cudaFuncAttributeMaxDynamicSharedMemorySize, SMEM1);

    // 1) zero scratch (mail / e_comb / n_comb)
    zero_scratch_kernel<<<(NN_ * D_ + 255) / 256, 256>>>();

    // 2) edge LSTM + mailbox scatter + e_comb
    lstm_gemm_kernel<0><<<E_ / 64, 256, SMEM0>>>(
        edge_feat, node_feat, g_repr, edge_h, edge_c,
        Wih_e, Whh_e, bih_e, bhh_e,
        src, dst, edge_graph,
        e_out, h_e, c_e, E_);

    // 3) node LSTM (consumes mail) + n_comb
    lstm_gemm_kernel<1><<<(NN_ + 63) / 64, 256, SMEM1>>>(
        node_feat, nullptr, g_repr, node_h, node_c,
        Wih_n, Whh_n, bih_n, bhh_n,
        nullptr, nullptr, node_graph,
        n_out, h_n, c_n, NN_);

    // 4) graph LSTM (consumes e_comb, n_comb)
    graph_lstm_kernel<<<B_, 256>>>(
        g_repr, graph_h, graph_c,
        Wih_u, Whh_u, bih_u, bhh_u,
        u_out, h_u, c_u);
}

// round 2
// speedup vs baseline: 2.8025x; 2.8025x over previous
#include <cuda_runtime.h>
#include <math.h>

// Problem constants
#define E_ 400000
#define NN_ 50000
#define B_ 50
#define D_ 64

#define KC 16          // k-chunk per smem W tile
#define WPAD 260       // padded gate-row stride for Ws[k][gate]

// scratch (device globals: no allocation allowed)
__device__ float g_mail[NN_ * D_];
__device__ float g_ecomb[B_ * D_];
__device__ float g_ncomb[B_ * D_];

__device__ __forceinline__ float sigmoidf_(float x) {
    return 1.0f / (1.0f + __expf(-x));
}

__device__ __forceinline__ unsigned long long pack2(float lo, float hi) {
    unsigned long long r;
    asm("mov.b64 %0, {%1, %2};" : "=l"(r) : "f"(lo), "f"(hi));
    return r;
}
__device__ __forceinline__ void unpack2(unsigned long long v, float& lo, float& hi) {
    asm("mov.b64 {%0, %1}, %2;" : "=f"(lo), "=f"(hi) : "l"(v));
}
// packed f32x2 FMA (B300 FFMA2 path — only reachable via PTX)
__device__ __forceinline__ void fma2(unsigned long long& acc, unsigned long long a, unsigned long long b) {
    asm("fma.rn.f32x2 %0, %1, %2, %0;" : "+l"(acc) : "l"(a), "l"(b));
}

// load chunk (k0..k0+KC) of W for all 256 gates into 4 float4 regs per thread
__device__ __forceinline__ void load_w_regs(
    const float* __restrict__ Wih, const float* __restrict__ Whh,
    int KIH, int k0, int tid, float4 (&pf)[4])
{
    #pragma unroll
    for (int t = 0; t < 4; ++t) {
        int idx = tid + t * 256;
        int g = idx >> 2;
        int c4 = (idx & 3) * 4;
        const float* p = (k0 < KIH)
            ? (Wih + (size_t)g * KIH + k0 + c4)
            : (Whh + (size_t)g * 64 + (k0 - KIH) + c4);
        pf[t] = *(const float4*)p;
    }
}

// transpose-store prefetched W regs into smem Ws[kc][gate] (padded WPAD)
__device__ __forceinline__ void store_w_smem(float* __restrict__ Ws, int tid, const float4 (&pf)[4])
{
    #pragma unroll
    for (int t = 0; t < 4; ++t) {
        int idx = tid + t * 256;
        int g = idx >> 2;
        int c4 = (idx & 3) * 4;
        Ws[(size_t)(c4 + 0) * WPAD + g] = pf[t].x;
        Ws[(size_t)(c4 + 1) * WPAD + g] = pf[t].y;
        Ws[(size_t)(c4 + 2) * WPAD + g] = pf[t].z;
        Ws[(size_t)(c4 + 3) * WPAD + g] = pf[t].w;
    }
}

// compute one KC-chunk: acc[m-pair][gate] += Xs[k][m] * Ws[k][g]
__device__ __forceinline__ void compute_chunk(
    const float* __restrict__ Ws, const float* __restrict__ xb,
    int rowA, int rowB, unsigned long long (&acc)[4][8])
{
    #pragma unroll 4
    for (int kc = 0; kc < KC; ++kc) {
        const float* xr = xb + kc * 64;
        ulonglong2 a = *(const ulonglong2*)xr;          // broadcast LDS.128
        ulonglong2 b = *(const ulonglong2*)(xr + 4);
        unsigned long long xm0 = a.x, xm1 = a.y, xm2 = b.x, xm3 = b.y;
        float4 wA = *(const float4*)&Ws[(size_t)kc * WPAD + rowA];  // LDS.128
        float4 wB = *(const float4*)&Ws[(size_t)kc * WPAD + rowB];
        float wa[4] = {wA.x, wA.y, wA.z, wA.w};
        float wb[4] = {wB.x, wB.y, wB.z, wB.w};
        #pragma unroll
        for (int j = 0; j < 4; ++j) {
            unsigned long long w2 = pack2(wa[j], wa[j]);
            fma2(acc[0][j], xm0, w2);
            fma2(acc[1][j], xm1, w2);
            fma2(acc[2][j], xm2, w2);
            fma2(acc[3][j], xm3, w2);
        }
        #pragma unroll
        for (int j = 0; j < 4; ++j) {
            unsigned long long w2 = pack2(wb[j], wb[j]);
            fma2(acc[0][4 + j], xm0, w2);
            fma2(acc[1][4 + j], xm1, w2);
            fma2(acc[2][4 + j], xm2, w2);
            fma2(acc[3][4 + j], xm3, w2);
        }
    }
}

// MODE 0: edge LSTM  (K=320: [edge_feat | nf[src] | nf[dst] | g_repr[eg] | edge_h])
// MODE 1: node LSTM  (K=256: [node_feat | mail | g_repr[ng] | node_h])
template <int MODE>
__global__ void __launch_bounds__(256, 2)
lstm_gemm_kernel(
    const float* __restrict__ feat,
    const float* __restrict__ nfeat,
    const float* __restrict__ grepr,
    const float* __restrict__ h_in,
    const float* __restrict__ c_in,
    const float* __restrict__ Wih,
    const float* __restrict__ Whh,
    const float* __restrict__ bih,
    const float* __restrict__ bhh,
    const int* __restrict__ src,
    const int* __restrict__ dst,
    const int* __restrict__ rgraph,
    float* __restrict__ out_r,
    float* __restrict__ out_h,
    float* __restrict__ out_c,
    int Mrows)
{
    constexpr int KTOT = (MODE == 0) ? 320 : 256;
    constexpr int KIH  = (MODE == 0) ? 256 : 192;
    constexpr int NC   = KTOT / KC;
    constexpr int BM = 64;

    extern __shared__ float sm[];
    float* Xs = sm;                          // [KTOT][64] transposed X tile
    float* rsum = sm + KTOT * 64;            // [2][64] per-graph reduction
    float* Ws = rsum + 128;                  // [KC][WPAD] W chunk
    float* gates_s = sm;                     // overlays Xs after GEMM: [64][256]

    const int tid = threadIdx.x;
    const int tx = tid & 31;
    const int ty = tid >> 5;
    const int m0 = blockIdx.x * BM;
    const float* nf = (MODE == 0) ? nfeat : (const float*)g_mail;
    float* combp = (MODE == 0) ? g_ecomb : g_ncomb;

    // ---- gather X into smem, transposed: Xs[k][m] ----
    for (int idx = tid; idx < BM * (KTOT / 4); idx += 256) {
        int m = idx & 63;
        int c4 = (idx >> 6) * 4;
        int row = m0 + m;
        float4 v = make_float4(0.f, 0.f, 0.f, 0.f);
        if (row < Mrows) {
            if (MODE == 0) {
                if (c4 < 64)        v = *(const float4*)&feat[(size_t)row * 64 + c4];
                else if (c4 < 128)  v = *(const float4*)&nf[(size_t)src[row] * 64 + (c4 - 64)];
                else if (c4 < 192)  v = *(const float4*)&nf[(size_t)dst[row] * 64 + (c4 - 128)];
                else if (c4 < 256)  v = *(const float4*)&grepr[(size_t)rgraph[row] * 64 + (c4 - 192)];
                else                v = *(const float4*)&h_in[(size_t)row * 64 + (c4 - 256)];
            } else {
                if (c4 < 64)        v = *(const float4*)&feat[(size_t)row * 64 + c4];
                else if (c4 < 128)  v = *(const float4*)&nf[(size_t)row * 64 + (c4 - 64)];
                else if (c4 < 192)  v = *(const float4*)&grepr[(size_t)rgraph[row] * 64 + (c4 - 128)];
                else                v = *(const float4*)&h_in[(size_t)row * 64 + (c4 - 192)];
            }
        }
        Xs[(size_t)(c4 + 0) * 64 + m] = v.x;
        Xs[(size_t)(c4 + 1) * 64 + m] = v.y;
        Xs[(size_t)(c4 + 2) * 64 + m] = v.z;
        Xs[(size_t)(c4 + 3) * 64 + m] = v.w;
    }

    unsigned long long acc[4][8];
    #pragma unroll
    for (int i = 0; i < 4; ++i)
        #pragma unroll
        for (int j = 0; j < 8; ++j) acc[i][j] = 0ull;

    const int rowA = tx * 4;          // gates [tx*4, tx*4+4)
    const int rowB = 128 + tx * 4;
    const int tyo = ty * 8;

    // ---- K loop: prefetch W chunk to regs, STS, compute (LDG c+1 overlaps compute c) ----
    float4 pf[4];
    load_w_regs(Wih, Whh, KIH, 0, tid, pf);
    #pragma unroll 1
    for (int c = 0; c < NC; ++c) {
        __syncthreads();                 // Ws free (and Xs staged on first iter)
        store_w_smem(Ws, tid, pf);
        __syncthreads();
        if (c + 1 < NC) load_w_regs(Wih, Whh, KIH, (c + 1) * KC, tid, pf);
        compute_chunk(Ws, Xs + (size_t)(c * KC) * 64 + tyo, rowA, rowB, acc);
    }

    __syncthreads();  // done reading Xs

    // unpack accumulators into gates smem: gates_s[m][g]
    #pragma unroll
    for (int i = 0; i < 4; ++i) {
        int m = ty * 8 + i * 2;
        #pragma unroll
        for (int j = 0; j < 8; ++j) {
            int g = (j < 4) ? (rowA + j) : (rowB + (j - 4));
            float lo, hi;
            unpack2(acc[i][j], lo, hi);
            gates_s[(size_t)m * 256 + g] = lo;
            gates_s[(size_t)(m + 1) * 256 + g] = hi;
        }
    }
    if (tid < 128) rsum[tid] = 0.f;
    __syncthreads();

    // ---- fused LSTM pointwise + scatter ----
    const int d = tid & 63;
    const float bi = bih[d] + bhh[d];
    const float bf = bih[64 + d] + bhh[64 + d];
    const float bg = bih[128 + d] + bhh[128 + d];
    const float bo = bih[192 + d] + bhh[192 + d];
    const int gfirst = rgraph[m0];
    const int mlast = (m0 + BM - 1 < Mrows) ? (m0 + BM - 1) : (Mrows - 1);
    const int glast = rgraph[mlast];

    float acc0 = 0.f, acc1 = 0.f;
    #pragma unroll 4
    for (int it = 0; it < 16; ++it) {
        int ml = it * 4 + (tid >> 6);
        int row = m0 + ml;
        if (row < Mrows) {
            float gi = gates_s[(size_t)ml * 256 + d] + bi;
            float gf = gates_s[(size_t)ml * 256 + 64 + d] + bf;
            float gg = gates_s[(size_t)ml * 256 + 128 + d] + bg;
            float go = gates_s[(size_t)ml * 256 + 192 + d] + bo;
            float c2 = sigmoidf_(gf) * c_in[(size_t)row * 64 + d] + sigmoidf_(gi) * tanhf(gg);
            float h = sigmoidf_(go) * tanhf(c2);
            float r = fmaxf(h, 0.f);
            out_r[(size_t)row * 64 + d] = r;
            out_h[(size_t)row * 64 + d] = h;
            out_c[(size_t)row * 64 + d] = c2;
            if (MODE == 0) {
                atomicAdd(&g_mail[(size_t)dst[row] * 64 + d], r);
            }
            int gr = rgraph[row];
            if (gr == gfirst) acc0 += r; else acc1 += r;
        }
    }
    atomicAdd(&rsum[d], acc0);
    atomicAdd(&rsum[64 + d], acc1);
    __syncthreads();
    if (tid < 64) {
        atomicAdd(&combp[(size_t)gfirst * 64 + tid], rsum[tid]);
    } else if (tid < 128 && glast != gfirst) {
        atomicAdd(&combp[(size_t)glast * 64 + (tid - 64)], rsum[tid]);
    }
}

// graph-level LSTM: B=50 graphs, one block each, float4 W loads for MLP
__global__ void graph_lstm_kernel(
    const float* __restrict__ grepr,
    const float* __restrict__ h_in,
    const float* __restrict__ c_in,
    const float* __restrict__ Wih,
    const float* __restrict__ Whh,
    const float* __restrict__ bih,
    const float* __restrict__ bhh,
    float* __restrict__ out_r,
    float* __restrict__ out_h,
    float* __restrict__ out_c)
{
    __shared__ float xu[256];   // [ncomb64 | ecomb64 | grepr64 | h64]
    __shared__ float gs[256];
    const int b = blockIdx.x;
    const int tid = threadIdx.x;

    if (tid < 64)       xu[tid] = g_ncomb[b * 64 + tid];
    else if (tid < 128) xu[tid] = g_ecomb[b * 64 + (tid - 64)];
    else if (tid < 192) xu[tid] = grepr[b * 64 + (tid - 128)];
    else                xu[tid] = h_in[b * 64 + (tid - 192)];
    __syncthreads();

    float a = bih[tid] + bhh[tid];
    const float* wih_row = Wih + (size_t)tid * 192;
    #pragma unroll 8
    for (int k4 = 0; k4 < 48; ++k4) {
        float4 w = *(const float4*)&wih_row[k4 * 4];
        a += w.x * xu[k4 * 4] + w.y * xu[k4 * 4 + 1] + w.z * xu[k4 * 4 + 2] + w.w * xu[k4 * 4 + 3];
    }
    const float* whh_row = Whh + (size_t)tid * 64;
    #pragma unroll 8
    for (int k4 = 0; k4 < 16; ++k4) {
        float4 w = *(const float4*)&whh_row[k4 * 4];
        a += w.x * xu[192 + k4 * 4] + w.y * xu[192 + k4 * 4 + 1]
           + w.z * xu[192 + k4 * 4 + 2] + w.w * xu[192 + k4 * 4 + 3];
    }
    gs[tid] = a;
    __syncthreads();

    if (tid < 64) {
        int dd = tid;
        float gi = gs[dd], gf = gs[64 + dd], gg = gs[128 + dd], go = gs[192 + dd];
        float c2 = sigmoidf_(gf) * c_in[b * 64 + dd] + sigmoidf_(gi) * tanhf(gg);
        float h = sigmoidf_(go) * tanhf(c2);
        out_r[b * 64 + dd] = fmaxf(h, 0.f);
        out_h[b * 64 + dd] = h;
        out_c[b * 64 + dd] = c2;
    }
}

__global__ void zero_scratch_kernel()
{
    int i = blockIdx.x * 256 + threadIdx.x;
    if (i < NN_ * D_) g_mail[i] = 0.f;
    if (i < B_ * D_) { g_ecomb[i] = 0.f; g_ncomb[i] = 0.f; }
}

extern "C" void kernel_launch(void* const* d_in, const int* in_sizes, int n_in,
                              void* d_out, int out_size)
{
    const float* edge_feat  = (const float*)d_in[0];
    const float* node_feat  = (const float*)d_in[1];
    const float* g_repr     = (const float*)d_in[2];
    const float* edge_h     = (const float*)d_in[3];
    const float* edge_c     = (const float*)d_in[4];
    const float* node_h     = (const float*)d_in[5];
    const float* node_c     = (const float*)d_in[6];
    const float* graph_h    = (const float*)d_in[7];
    const float* graph_c    = (const float*)d_in[8];
    const float* Wih_e      = (const float*)d_in[9];
    const float* Whh_e      = (const float*)d_in[10];
    const float* bih_e      = (const float*)d_in[11];
    const float* bhh_e      = (const float*)d_in[12];
    const float* Wih_n      = (const float*)d_in[13];
    const float* Whh_n      = (const float*)d_in[14];
    const float* bih_n      = (const float*)d_in[15];
    const float* bhh_n      = (const float*)d_in[16];
    const float* Wih_u      = (const float*)d_in[17];
    const float* Whh_u      = (const float*)d_in[18];
    const float* bih_u      = (const float*)d_in[19];
    const float* bhh_u      = (const float*)d_in[20];
    const int*   src        = (const int*)d_in[21];
    const int*   dst        = (const int*)d_in[22];
    const int*   edge_graph = (const int*)d_in[23];
    const int*   node_graph = (const int*)d_in[24];

    float* out = (float*)d_out;
    const size_t ED = (size_t)E_ * D_;
    const size_t ND = (size_t)NN_ * D_;
    const size_t BD = (size_t)B_ * D_;
    float* e_out = out;
    float* h_e   = out + ED;
    float* c_e   = out + 2 * ED;
    float* n_out = out + 3 * ED;
    float* h_n   = n_out + ND;
    float* c_n   = n_out + 2 * ND;
    float* u_out = n_out + 3 * ND;
    float* h_u   = u_out + BD;
    float* c_u   = u_out + 2 * BD;

    const int SMEM0 = (320 * 64 + 128 + KC * WPAD) * 4;  // 99072 B (edge)
    const int SMEM1 = (256 * 64 + 128 + KC * WPAD) * 4;  // 82688 B (node)
    cudaFuncSetAttribute(lstm_gemm_kernel<0>, cudaFuncAttributeMaxDynamicSharedMemorySize, SMEM0);
    cudaFuncSetAttribute(lstm_gemm_kernel<1>, cudaFuncAttributeMaxDynamicSharedMemorySize, SMEM1);

    // 1) zero scratch (mail / e_comb / n_comb)
    zero_scratch_kernel<<<(NN_ * D_ + 255) / 256, 256>>>();

    // 2) edge LSTM + mailbox scatter + e_comb
    lstm_gemm_kernel<0><<<E_ / 64, 256, SMEM0>>>(
        edge_feat, node_feat, g_repr, edge_h, edge_c,
        Wih_e, Whh_e, bih_e, bhh_e,
        src, dst, edge_graph,
        e_out, h_e, c_e, E_);

    // 3) node LSTM (consumes mail) + n_comb
    lstm_gemm_kernel<1><<<(NN_ + 63) / 64, 256, SMEM1>>>(
        node_feat, nullptr, g_repr, node_h, node_c,
        Wih_n, Whh_n, bih_n, bhh_n,
        nullptr, nullptr, node_graph,
        n_out, h_n, c_n, NN_);

    // 4) graph LSTM (consumes e_comb, n_comb)
    graph_lstm_kernel<<<B_, 256>>>(
        g_repr, graph_h, graph_c,
        Wih_u, Whh_u, bih_u, bhh_u,
        u_out, h_u, c_u);
}

// round 4
// speedup vs baseline: 3.0995x; 1.1060x over previous
#include <cuda_runtime.h>
#include <cuda_bf16.h>
#include <math.h>
#include <stdint.h>

#define E_ 400000
#define NN_ 50000
#define B_ 50

// ---------------- device scratch (no allocs allowed) ----------------
__device__ float g_mail[NN_ * 64];
__device__ float g_ecomb[B_ * 64];
__device__ float g_ncomb[B_ * 64];
__device__ __align__(16) __nv_bfloat16 g_Whi_e[256 * 320];
__device__ __align__(16) __nv_bfloat16 g_Wlo_e[256 * 320];
__device__ __align__(16) __nv_bfloat16 g_Whi_n[256 * 256];
__device__ __align__(16) __nv_bfloat16 g_Wlo_n[256 * 256];

// ---------------- smem layout (bytes) ----------------
// rows padded to 72 bf16 = 144 B (conflict-free ldmatrix/STS)
#define OFF_BIAS 0                    // 256 f32
#define OFF_RSUM 1024                 // 128 f32
#define OFF_A    2048                 // A[buf][hl] : 128*144 = 18432 each
#define ABUF(buf, hl) (OFF_A + (buf) * 36864 + (hl) * 18432)
#define OFF_B    75776                // B[buf][hl] : 256*144 = 36864 each
#define BBUF(buf, hl) (OFF_B + (buf) * 73728 + (hl) * 36864)
#define SMEM_SZ  223232
#define OFF_GATES 2048                // overlay after GEMM: 128 x 260 f32

// ---------------- PTX helpers (baseline sm_80-class only) ----------------
__device__ __forceinline__ uint32_t smem_u32(const void* p) {
    uint32_t a;
    asm("{ .reg .u64 t; cvta.to.shared.u64 t, %1; cvt.u32.u64 %0, t; }" : "=r"(a) : "l"(p));
    return a;
}
#define CP_ASYNC16(dst, src) \
    asm volatile("cp.async.ca.shared.global [%0], [%1], 16;" :: "r"(dst), "l"(src))
#define CP_COMMIT() asm volatile("cp.async.commit_group;" ::: "memory")
#define CP_WAIT0()  asm volatile("cp.async.wait_group 0;" ::: "memory")

__device__ __forceinline__ void ldsm4(uint32_t* r, uint32_t a) {
    asm volatile("ldmatrix.sync.aligned.m8n8.x4.shared.b16 {%0,%1,%2,%3}, [%4];"
        : "=r"(r[0]), "=r"(r[1]), "=r"(r[2]), "=r"(r[3]) : "r"(a));
}
__device__ __forceinline__ void mma16816(float* d, const uint32_t* a, uint32_t b0, uint32_t b1) {
    asm volatile("mma.sync.aligned.m16n8k16.row.col.f32.bf16.bf16.f32 "
        "{%0,%1,%2,%3},{%4,%5,%6,%7},{%8,%9},{%0,%1,%2,%3};"
        : "+f"(d[0]), "+f"(d[1]), "+f"(d[2]), "+f"(d[3])
        : "r"(a[0]), "r"(a[1]), "r"(a[2]), "r"(a[3]), "r"(b0), "r"(b1));
}

// ---------------- math helpers ----------------
__device__ __forceinline__ float sigm(float x) { return 1.0f / (1.0f + __expf(-x)); }
__device__ __forceinline__ float tanh_(float x) {
    return __fdividef(2.0f, 1.0f + __expf(-2.0f * x)) - 1.0f;
}
__device__ __forceinline__ void split2(float a, float b, uint32_t& hi, uint32_t& lo) {
    __nv_bfloat16 h0 = __float2bfloat16(a), h1 = __float2bfloat16(b);
    float r0 = a - __bfloat162float(h0), r1 = b - __bfloat162float(h1);
    __nv_bfloat16 l0 = __float2bfloat16(r0), l1 = __float2bfloat16(r1);
    hi = ((uint32_t)__bfloat16_as_ushort(h1) << 16) | __bfloat16_as_ushort(h0);
    lo = ((uint32_t)__bfloat16_as_ushort(l1) << 16) | __bfloat16_as_ushort(l0);
}

// ---------------- building blocks ----------------
// B chunk (256 gates x 64 k, hi+lo bf16) via cp.async (weights pre-split K-major)
__device__ __forceinline__ void issue_B(uint32_t smb, int off_hi, int off_lo,
    const __nv_bfloat16* __restrict__ Whi, const __nv_bfloat16* __restrict__ Wlo,
    int KTOT, int c, int tid)
{
    #pragma unroll
    for (int t = 0; t < 8; ++t) {
        int idx = tid + t * 256;
        int g = idx >> 3, seg = idx & 7;
        CP_ASYNC16(smb + off_hi + g * 144 + seg * 16,
                   (const char*)(Whi + (size_t)g * KTOT + c * 64 + seg * 8));
    }
    #pragma unroll
    for (int t = 0; t < 8; ++t) {
        int idx = tid + t * 256;
        int g = idx >> 3, seg = idx & 7;
        CP_ASYNC16(smb + off_lo + g * 144 + seg * 16,
                   (const char*)(Wlo + (size_t)g * KTOT + c * 64 + seg * 8));
    }
}

// A chunk gather (128 rows x 64 f32) -> bf16 hi/lo split -> padded STS
template <int MODE>
__device__ __forceinline__ void gather_A(char* sm, int off_hi, int off_lo,
    int c, int m0, int Mrows, int tid,
    const float* __restrict__ feat, const float* __restrict__ nfeat,
    const float* __restrict__ grepr, const float* __restrict__ h_in,
    const int* __restrict__ srcI, const int* __restrict__ dstI,
    const int* __restrict__ rgraph)
{
    #pragma unroll
    for (int t = 0; t < 8; ++t) {
        int idx = tid + t * 256;
        int rl = idx >> 4, q = idx & 15;
        int grow = m0 + rl;
        float4 v = make_float4(0.f, 0.f, 0.f, 0.f);
        if (grow < Mrows) {
            const float* p;
            if (MODE == 0) {
                if      (c == 0) p = feat  + (size_t)grow * 64;
                else if (c == 1) p = nfeat + (size_t)srcI[grow] * 64;
                else if (c == 2) p = nfeat + (size_t)dstI[grow] * 64;
                else if (c == 3) p = grepr + (size_t)rgraph[grow] * 64;
                else             p = h_in  + (size_t)grow * 64;
            } else {
                if      (c == 0) p = feat  + (size_t)grow * 64;
                else if (c == 1) p = (const float*)g_mail + (size_t)grow * 64;
                else if (c == 2) p = grepr + (size_t)rgraph[grow] * 64;
                else             p = h_in  + (size_t)grow * 64;
            }
            v = *(const float4*)(p + q * 4);
        }
        uint32_t h01, l01, h23, l23;
        split2(v.x, v.y, h01, l01);
        split2(v.z, v.w, h23, l23);
        int o = rl * 144 + q * 8;
        *(uint2*)(sm + off_hi + o) = make_uint2(h01, h23);
        *(uint2*)(sm + off_lo + o) = make_uint2(l01, l23);
    }
}

// one bf16 pass over a k64 chunk: warp tile M64 x N64
__device__ __forceinline__ void do_pass(uint32_t aB, uint32_t bB,
                                        uint32_t aoff, uint32_t boff,
                                        float (&acc)[4][8][4])
{
    #pragma unroll
    for (int kt = 0; kt < 4; ++kt) {
        uint32_t a[4][4];
        #pragma unroll
        for (int mt = 0; mt < 4; ++mt) ldsm4(a[mt], aB + aoff + mt * 2304 + kt * 32);
        uint32_t b4[4][4];
        #pragma unroll
        for (int g = 0; g < 4; ++g) ldsm4(b4[g], bB + boff + g * 2304 + kt * 32);
        #pragma unroll
        for (int mt = 0; mt < 4; ++mt)
            #pragma unroll
            for (int g = 0; g < 4; ++g) {
                mma16816(acc[mt][2 * g],     a[mt], b4[g][0], b4[g][2]);
                mma16816(acc[mt][2 * g + 1], a[mt], b4[g][1], b4[g][3]);
            }
    }
}

// MODE 0: edge LSTM (K=320: feat | nf[src] | nf[dst] | grepr | h)
// MODE 1: node LSTM (K=256: feat | mail | grepr | h)
template <int MODE>
__global__ void __launch_bounds__(256, 1)
lstm_mma_kernel(const float* __restrict__ feat,
                const float* __restrict__ nfeat,
                const float* __restrict__ grepr,
                const float* __restrict__ h_in,
                const float* __restrict__ c_in,
                const float* __restrict__ bih,
                const float* __restrict__ bhh,
                const int* __restrict__ srcI,
                const int* __restrict__ dstI,
                const int* __restrict__ rgraph,
                float* __restrict__ out_r,
                float* __restrict__ out_h,
                float* __restrict__ out_c,
                int Mrows)
{
    constexpr int KTOT = (MODE == 0) ? 320 : 256;
    constexpr int NC = KTOT / 64;
    extern __shared__ char sm[];
    const uint32_t smb = smem_u32(sm);
    float* bias_s  = (float*)(sm + OFF_BIAS);
    float* rsum    = (float*)(sm + OFF_RSUM);
    float* gates_s = (float*)(sm + OFF_GATES);

    const int tid = threadIdx.x;
    const int lane = tid & 31;
    const int wid = tid >> 5;
    const int m0 = blockIdx.x * 128;
    const __nv_bfloat16* Whi = (MODE == 0) ? g_Whi_e : g_Whi_n;
    const __nv_bfloat16* Wlo = (MODE == 0) ? g_Wlo_e : g_Wlo_n;

    bias_s[tid] = bih[tid] + bhh[tid];
    if (tid < 128) rsum[tid] = 0.f;

    // prologue: stage chunk 0
    issue_B(smb, BBUF(0, 0), BBUF(0, 1), Whi, Wlo, KTOT, 0, tid);
    CP_COMMIT();
    gather_A<MODE>(sm, ABUF(0, 0), ABUF(0, 1), 0, m0, Mrows, tid,
                   feat, nfeat, grepr, h_in, srcI, dstI, rgraph);
    CP_WAIT0();
    __syncthreads();

    float acc[4][8][4];
    #pragma unroll
    for (int i = 0; i < 4; ++i)
        #pragma unroll
        for (int j = 0; j < 8; ++j)
            #pragma unroll
            for (int k = 0; k < 4; ++k) acc[i][j][k] = 0.f;

    const int wm = wid & 1, wn = wid >> 1;
    const uint32_t aoff = (uint32_t)((wm * 64 + (lane & 15)) * 144 + (lane >> 4) * 16);
    const uint32_t boff = (uint32_t)((wn * 64 + (lane & 15)) * 144 + (lane >> 4) * 16);

    #pragma unroll 1
    for (int c = 0; c < NC; ++c) {
        const int cur = c & 1, nxt = cur ^ 1;
        if (c + 1 < NC) {
            issue_B(smb, BBUF(nxt, 0), BBUF(nxt, 1), Whi, Wlo, KTOT, c + 1, tid);
            CP_COMMIT();
        }
        const uint32_t aHi = smb + ABUF(cur, 0), aLo = smb + ABUF(cur, 1);
        const uint32_t bHi = smb + BBUF(cur, 0), bLo = smb + BBUF(cur, 1);
        do_pass(aHi, bHi, aoff, boff, acc);           // hi*hi
        if (c + 1 < NC)
            gather_A<MODE>(sm, ABUF(nxt, 0), ABUF(nxt, 1), c + 1, m0, Mrows, tid,
                           feat, nfeat, grepr, h_in, srcI, dstI, rgraph);
        do_pass(aLo, bHi, aoff, boff, acc);           // lo*hi
        do_pass(aHi, bLo, aoff, boff, acc);           // hi*lo
        if (c + 1 < NC) CP_WAIT0();
        __syncthreads();
    }

    // ---- acc -> gates_s[m][260] (overlays A/B smem) ----
    #pragma unroll
    for (int mt = 0; mt < 4; ++mt) {
        int r0 = wm * 64 + mt * 16 + (lane >> 2);
        #pragma unroll
        for (int nt = 0; nt < 8; ++nt) {
            int nc = wn * 64 + nt * 8 + (lane & 3) * 2;
            *(float2*)&gates_s[r0 * 260 + nc]       = make_float2(acc[mt][nt][0], acc[mt][nt][1]);
            *(float2*)&gates_s[(r0 + 8) * 260 + nc] = make_float2(acc[mt][nt][2], acc[mt][nt][3]);
        }
    }
    __syncthreads();

    // ---- fused LSTM pointwise + mailbox scatter + per-graph sums ----
    const int d = tid & 63;
    const float bi = bias_s[d], bf = bias_s[64 + d], bg = bias_s[128 + d], bo = bias_s[192 + d];
    const int gfirst = rgraph[m0];
    int mlast = (m0 + 127 < Mrows) ? (m0 + 127) : (Mrows - 1);
    const int glast = rgraph[mlast];
    float a0 = 0.f, a1 = 0.f;
    #pragma unroll 4
    for (int it = 0; it < 32; ++it) {
        int ml = it * 4 + (tid >> 6);
        int grow = m0 + ml;
        if (grow < Mrows) {
            float gi = gates_s[ml * 260 + d] + bi;
            float gf = gates_s[ml * 260 + 64 + d] + bf;
            float gg = gates_s[ml * 260 + 128 + d] + bg;
            float go = gates_s[ml * 260 + 192 + d] + bo;
            float c2 = sigm(gf) * c_in[(size_t)grow * 64 + d] + sigm(gi) * tanh_(gg);
            float h = sigm(go) * tanh_(c2);
            float r = fmaxf(h, 0.f);
            out_r[(size_t)grow * 64 + d] = r;
            out_h[(size_t)grow * 64 + d] = h;
            out_c[(size_t)grow * 64 + d] = c2;
            if (MODE == 0) atomicAdd(&g_mail[(size_t)dstI[grow] * 64 + d], r);
            if (rgraph[grow] == gfirst) a0 += r; else a1 += r;
        }
    }
    atomicAdd(&rsum[d], a0);
    atomicAdd(&rsum[64 + d], a1);
    __syncthreads();
    float* comb = (MODE == 0) ? g_ecomb : g_ncomb;
    if (tid < 64) atomicAdd(&comb[(size_t)gfirst * 64 + tid], rsum[tid]);
    else if (tid < 128 && glast != gfirst)
        atomicAdd(&comb[(size_t)glast * 64 + (tid - 64)], rsum[tid]);
}

// ---------------- W pre-split (fp32 -> bf16 hi/lo, K-major concat) ----------------
__global__ void splitw_kernel(const float* __restrict__ Wih_e, const float* __restrict__ Whh_e,
                              const float* __restrict__ Wih_n, const float* __restrict__ Whh_n)
{
    int i = blockIdx.x * 256 + threadIdx.x;
    if (i < 256 * 320) {
        int g = i / 320, k = i - g * 320;
        float v = (k < 256) ? Wih_e[g * 256 + k] : Whh_e[g * 64 + (k - 256)];
        __nv_bfloat16 h = __float2bfloat16(v);
        g_Whi_e[i] = h;
        g_Wlo_e[i] = __float2bfloat16(v - __bfloat162float(h));
    }
    if (i < 256 * 256) {
        int g = i >> 8, k = i & 255;
        float v = (k < 192) ? Wih_n[g * 192 + k] : Whh_n[g * 64 + (k - 192)];
        __nv_bfloat16 h = __float2bfloat16(v);
        g_Whi_n[i] = h;
        g_Wlo_n[i] = __float2bfloat16(v - __bfloat162float(h));
    }
}

__global__ void zero_scratch_kernel()
{
    int i = blockIdx.x * 256 + threadIdx.x;
    if (i < NN_ * 64) g_mail[i] = 0.f;
    if (i < B_ * 64) { g_ecomb[i] = 0.f; g_ncomb[i] = 0.f; }
}

// ---------------- graph-level LSTM (B=50) ----------------
__global__ void graph_lstm_kernel(
    const float* __restrict__ grepr,
    const float* __restrict__ h_in,
    const float* __restrict__ c_in,
    const float* __restrict__ Wih,
    const float* __restrict__ Whh,
    const float* __restrict__ bih,
    const float* __restrict__ bhh,
    float* __restrict__ out_r,
    float* __restrict__ out_h,
    float* __restrict__ out_c)
{
    __shared__ float xu[256];
    __shared__ float gs[256];
    const int b = blockIdx.x;
    const int tid = threadIdx.x;

    if (tid < 64)       xu[tid] = g_ncomb[b * 64 + tid];
    else if (tid < 128) xu[tid] = g_ecomb[b * 64 + (tid - 64)];
    else if (tid < 192) xu[tid] = grepr[b * 64 + (tid - 128)];
    else                xu[tid] = h_in[b * 64 + (tid - 192)];
    __syncthreads();

    float a = bih[tid] + bhh[tid];
    const float* wih_row = Wih + (size_t)tid * 192;
    #pragma unroll 8
    for (int k4 = 0; k4 < 48; ++k4) {
        float4 w = *(const float4*)&wih_row[k4 * 4];
        a += w.x * xu[k4 * 4] + w.y * xu[k4 * 4 + 1] + w.z * xu[k4 * 4 + 2] + w.w * xu[k4 * 4 + 3];
    }
    const float* whh_row = Whh + (size_t)tid * 64;
    #pragma unroll 8
    for (int k4 = 0; k4 < 16; ++k4) {
        float4 w = *(const float4*)&whh_row[k4 * 4];
        a += w.x * xu[192 + k4 * 4] + w.y * xu[192 + k4 * 4 + 1]
           + w.z * xu[192 + k4 * 4 + 2] + w.w * xu[192 + k4 * 4 + 3];
    }
    gs[tid] = a;
    __syncthreads();

    if (tid < 64) {
        float gi = gs[tid], gf = gs[64 + tid], gg = gs[128 + tid], go = gs[192 + tid];
        float c2 = sigm(gf) * c_in[b * 64 + tid] + sigm(gi) * tanh_(gg);
        float h = sigm(go) * tanh_(c2);
        out_r[b * 64 + tid] = fmaxf(h, 0.f);
        out_h[b * 64 + tid] = h;
        out_c[b * 64 + tid] = c2;
    }
}

extern "C" void kernel_launch(void* const* d_in, const int* in_sizes, int n_in,
                              void* d_out, int out_size)
{
    const float* edge_feat  = (const float*)d_in[0];
    const float* node_feat  = (const float*)d_in[1];
    const float* g_repr     = (const float*)d_in[2];
    const float* edge_h     = (const float*)d_in[3];
    const float* edge_c     = (const float*)d_in[4];
    const float* node_h     = (const float*)d_in[5];
    const float* node_c     = (const float*)d_in[6];
    const float* graph_h    = (const float*)d_in[7];
    const float* graph_c    = (const float*)d_in[8];
    const float* Wih_e      = (const float*)d_in[9];
    const float* Whh_e      = (const float*)d_in[10];
    const float* bih_e      = (const float*)d_in[11];
    const float* bhh_e      = (const float*)d_in[12];
    const float* Wih_n      = (const float*)d_in[13];
    const float* Whh_n      = (const float*)d_in[14];
    const float* bih_n      = (const float*)d_in[15];
    const float* bhh_n      = (const float*)d_in[16];
    const float* Wih_u      = (const float*)d_in[17];
    const float* Whh_u      = (const float*)d_in[18];
    const float* bih_u      = (const float*)d_in[19];
    const float* bhh_u      = (const float*)d_in[20];
    const int*   src        = (const int*)d_in[21];
    const int*   dst        = (const int*)d_in[22];
    const int*   edge_graph = (const int*)d_in[23];
    const int*   node_graph = (const int*)d_in[24];

    float* out = (float*)d_out;
    const size_t ED = (size_t)E_ * 64;
    const size_t ND = (size_t)NN_ * 64;
    const size_t BD = (size_t)B_ * 64;
    float* e_out = out;
    float* h_e   = out + ED;
    float* c_e   = out + 2 * ED;
    float* n_out = out + 3 * ED;
    float* h_n   = n_out + ND;
    float* c_n   = n_out + 2 * ND;
    float* u_out = n_out + 3 * ND;
    float* h_u   = u_out + BD;
    float* c_u   = u_out + 2 * BD;

    cudaFuncSetAttribute(lstm_mma_kernel<0>, cudaFuncAttributeMaxDynamicSharedMemorySize, SMEM_SZ);
    cudaFuncSetAttribute(lstm_mma_kernel<1>, cudaFuncAttributeMaxDynamicSharedMemorySize, SMEM_SZ);

    // 1) W pre-split + scratch zero
    splitw_kernel<<<320, 256>>>(Wih_e, Whh_e, Wih_n, Whh_n);
    zero_scratch_kernel<<<(NN_ * 64 + 255) / 256, 256>>>();

    // 2) edge LSTM (mma.sync bf16 3-pass) + mailbox scatter + e_comb
    lstm_mma_kernel<0><<<E_ / 128, 256, SMEM_SZ>>>(
        edge_feat, node_feat, g_repr, edge_h, edge_c,
        bih_e, bhh_e, src, dst, edge_graph,
        e_out, h_e, c_e, E_);

    // 3) node LSTM (consumes mail) + n_comb
    lstm_mma_kernel<1><<<(NN_ + 127) / 128, 256, SMEM_SZ>>>(
        node_feat, nullptr, g_repr, node_h, node_c,
        bih_n, bhh_n, nullptr, nullptr, node_graph,
        n_out, h_n, c_n, NN_);

    // 4) graph LSTM
    graph_lstm_kernel<<<B_, 256>>>(
        g_repr, graph_h, graph_c,
        Wih_u, Whh_u, bih_u, bhh_u,
        u_out, h_u, c_u);
}

// round 5
// speedup vs baseline: 4.5623x; 1.4720x over previous
#include <cuda_runtime.h>
#include <cuda_bf16.h>
#include <math.h>
#include <stdint.h>

#define E_ 400000
#define NN_ 50000
#define B_ 50

// ---------------- device scratch (no allocs allowed) ----------------
__device__ float g_mail[NN_ * 64];
__device__ float g_ecomb[B_ * 64];
__device__ float g_ncomb[B_ * 64];
__device__ __align__(16) __nv_bfloat16 g_Whi_e[256 * 320];
__device__ __align__(16) __nv_bfloat16 g_Wlo_e[256 * 320];
__device__ __align__(16) __nv_bfloat16 g_Whi_n[256 * 256];
__device__ __align__(16) __nv_bfloat16 g_Wlo_n[256 * 256];

// ---------------- smem layout (bytes), rows padded to 80 B ----------------
#define OFF_BIAS 0                     // 256 f32
#define OFF_RSUM 1024                  // 128 f32
#define OFF_A    1536                  // A[buf][hl]: 64*80 = 5120 each
#define ABUF(buf, hl) (OFF_A + ((buf) * 2 + (hl)) * 5120)
#define OFF_B    22016                 // B[buf][hl]: 256*80 = 20480 each
#define BBUF(buf, hl) (OFF_B + ((buf) * 2 + (hl)) * 20480)
#define SMEM_SZ  103936
#define OFF_GATES 1536                 // overlay after GEMM: 64 x 260 f32

// ---------------- PTX helpers (baseline sm_80-class only) ----------------
__device__ __forceinline__ uint32_t smem_u32(const void* p) {
    uint32_t a;
    asm("{ .reg .u64 t; cvta.to.shared.u64 t, %1; cvt.u32.u64 %0, t; }" : "=r"(a) : "l"(p));
    return a;
}
#define CP_ASYNC16(dst, src) \
    asm volatile("cp.async.ca.shared.global [%0], [%1], 16;" :: "r"(dst), "l"(src))
#define CP_COMMIT() asm volatile("cp.async.commit_group;" ::: "memory")
#define CP_WAIT0()  asm volatile("cp.async.wait_group 0;" ::: "memory")

__device__ __forceinline__ void ldsm4(uint32_t* r, uint32_t a) {
    asm volatile("ldmatrix.sync.aligned.m8n8.x4.shared.b16 {%0,%1,%2,%3}, [%4];"
        : "=r"(r[0]), "=r"(r[1]), "=r"(r[2]), "=r"(r[3]) : "r"(a));
}
__device__ __forceinline__ void mma16816(float* d, const uint32_t* a, uint32_t b0, uint32_t b1) {
    asm volatile("mma.sync.aligned.m16n8k16.row.col.f32.bf16.bf16.f32 "
        "{%0,%1,%2,%3},{%4,%5,%6,%7},{%8,%9},{%0,%1,%2,%3};"
        : "+f"(d[0]), "+f"(d[1]), "+f"(d[2]), "+f"(d[3])
        : "r"(a[0]), "r"(a[1]), "r"(a[2]), "r"(a[3]), "r"(b0), "r"(b1));
}

// ---------------- math helpers ----------------
__device__ __forceinline__ float sigm(float x) { return 1.0f / (1.0f + __expf(-x)); }
__device__ __forceinline__ float tanh_(float x) {
    return __fdividef(2.0f, 1.0f + __expf(-2.0f * x)) - 1.0f;
}
__device__ __forceinline__ void split2(float a, float b, uint32_t& hi, uint32_t& lo) {
    __nv_bfloat16 h0 = __float2bfloat16(a), h1 = __float2bfloat16(b);
    float r0 = a - __bfloat162float(h0), r1 = b - __bfloat162float(h1);
    __nv_bfloat16 l0 = __float2bfloat16(r0), l1 = __float2bfloat16(r1);
    hi = ((uint32_t)__bfloat16_as_ushort(h1) << 16) | __bfloat16_as_ushort(h0);
    lo = ((uint32_t)__bfloat16_as_ushort(l1) << 16) | __bfloat16_as_ushort(l0);
}

// segment pointer for the concatenated X (K in 32-wide sub-chunks)
template <int MODE>
__device__ __forceinline__ const float* seg_ptr(int c, int grow,
    const float* __restrict__ feat, const float* __restrict__ nfeat,
    const float* __restrict__ grepr, const float* __restrict__ h_in,
    const int* __restrict__ srcI, const int* __restrict__ dstI,
    const int* __restrict__ rgraph)
{
    int s = c >> 1;
    if (MODE == 0) {
        if (s == 0) return feat  + (size_t)grow * 64;
        if (s == 1) return nfeat + (size_t)srcI[grow] * 64;
        if (s == 2) return nfeat + (size_t)dstI[grow] * 64;
        if (s == 3) return grepr + (size_t)rgraph[grow] * 64;
        return h_in + (size_t)grow * 64;
    } else {
        if (s == 0) return feat + (size_t)grow * 64;
        if (s == 1) return (const float*)g_mail + (size_t)grow * 64;
        if (s == 2) return grepr + (size_t)rgraph[grow] * 64;
        return h_in + (size_t)grow * 64;
    }
}

// prefetch A sub-chunk (64 rows x 32 f32) into 2 float4 regs per thread
template <int MODE>
__device__ __forceinline__ void pf_A(float4 (&pf)[2], int c, int m0, int Mrows, int tid,
    const float* __restrict__ feat, const float* __restrict__ nfeat,
    const float* __restrict__ grepr, const float* __restrict__ h_in,
    const int* __restrict__ srcI, const int* __restrict__ dstI,
    const int* __restrict__ rgraph)
{
    #pragma unroll
    for (int t = 0; t < 2; ++t) {
        int idx = tid + t * 256;
        int rl = idx >> 3, q = idx & 7;
        int grow = m0 + rl;
        pf[t] = make_float4(0.f, 0.f, 0.f, 0.f);
        if (grow < Mrows) {
            const float* p = seg_ptr<MODE>(c, grow, feat, nfeat, grepr, h_in, srcI, dstI, rgraph);
            pf[t] = *(const float4*)(p + (c & 1) * 32 + q * 4);
        }
    }
}
// split + store prefetched A into padded smem (80 B rows)
__device__ __forceinline__ void st_A(const float4 (&pf)[2], char* sm, int off_hi, int off_lo, int tid)
{
    #pragma unroll
    for (int t = 0; t < 2; ++t) {
        int idx = tid + t * 256;
        int rl = idx >> 3, q = idx & 7;
        uint32_t h01, l01, h23, l23;
        split2(pf[t].x, pf[t].y, h01, l01);
        split2(pf[t].z, pf[t].w, h23, l23);
        int o = rl * 80 + q * 8;
        *(uint2*)(sm + off_hi + o) = make_uint2(h01, h23);
        *(uint2*)(sm + off_lo + o) = make_uint2(l01, l23);
    }
}

// B sub-chunk (256 gates x 32 k, hi+lo) via cp.async
__device__ __forceinline__ void issue_B(uint32_t smb, int off_hi, int off_lo,
    const __nv_bfloat16* __restrict__ Whi, const __nv_bfloat16* __restrict__ Wlo,
    int KTOT, int c, int tid)
{
    #pragma unroll
    for (int t = 0; t < 4; ++t) {
        int idx = tid + t * 256;
        int g = idx >> 2, s16 = idx & 3;
        CP_ASYNC16(smb + off_hi + g * 80 + s16 * 16,
                   (const char*)(Whi + (size_t)g * KTOT + c * 32 + s16 * 8));
    }
    #pragma unroll
    for (int t = 0; t < 4; ++t) {
        int idx = tid + t * 256;
        int g = idx >> 2, s16 = idx & 3;
        CP_ASYNC16(smb + off_lo + g * 80 + s16 * 16,
                   (const char*)(Wlo + (size_t)g * KTOT + c * 32 + s16 * 8));
    }
}

// merged 3-pass mma over one K=32 sub-chunk; warp tile 32x64, acc[2][8][4]
__device__ __forceinline__ void compute32(uint32_t smb, int aHi, int aLo, int bHi, int bLo,
                                          uint32_t aoff, uint32_t boff, float (&acc)[2][8][4])
{
    // hi*hi + lo*hi (bHi fragments reused)
    #pragma unroll
    for (int kt = 0; kt < 2; ++kt) {
        uint32_t b4[4][4];
        #pragma unroll
        for (int g = 0; g < 4; ++g) ldsm4(b4[g], smb + bHi + boff + g * 1280 + kt * 32);
        #pragma unroll
        for (int mt = 0; mt < 2; ++mt) {
            uint32_t a[4];
            ldsm4(a, smb + aHi + aoff + mt * 1280 + kt * 32);
            #pragma unroll
            for (int g = 0; g < 4; ++g) {
                mma16816(acc[mt][2 * g],     a, b4[g][0], b4[g][2]);
                mma16816(acc[mt][2 * g + 1], a, b4[g][1], b4[g][3]);
            }
            ldsm4(a, smb + aLo + aoff + mt * 1280 + kt * 32);
            #pragma unroll
            for (int g = 0; g < 4; ++g) {
                mma16816(acc[mt][2 * g],     a, b4[g][0], b4[g][2]);
                mma16816(acc[mt][2 * g + 1], a, b4[g][1], b4[g][3]);
            }
        }
    }
    // hi*lo
    #pragma unroll
    for (int kt = 0; kt < 2; ++kt) {
        uint32_t b4[4][4];
        #pragma unroll
        for (int g = 0; g < 4; ++g) ldsm4(b4[g], smb + bLo + boff + g * 1280 + kt * 32);
        #pragma unroll
        for (int mt = 0; mt < 2; ++mt) {
            uint32_t a[4];
            ldsm4(a, smb + aHi + aoff + mt * 1280 + kt * 32);
            #pragma unroll
            for (int g = 0; g < 4; ++g) {
                mma16816(acc[mt][2 * g],     a, b4[g][0], b4[g][2]);
                mma16816(acc[mt][2 * g + 1], a, b4[g][1], b4[g][3]);
            }
        }
    }
}

// MODE 0: edge LSTM (K=320) / MODE 1: node LSTM (K=256); CTA tile 64 x 256
template <int MODE>
__global__ void __launch_bounds__(256, 2)
lstm_mma_kernel(const float* __restrict__ feat,
                const float* __restrict__ nfeat,
                const float* __restrict__ grepr,
                const float* __restrict__ h_in,
                const float* __restrict__ c_in,
                const float* __restrict__ bih,
                const float* __restrict__ bhh,
                const int* __restrict__ srcI,
                const int* __restrict__ dstI,
                const int* __restrict__ rgraph,
                float* __restrict__ out_r,
                float* __restrict__ out_h,
                float* __restrict__ out_c,
                int Mrows)
{
    constexpr int KTOT = (MODE == 0) ? 320 : 256;
    constexpr int NC = KTOT / 32;
    extern __shared__ char sm[];
    const uint32_t smb = smem_u32(sm);
    float* bias_s  = (float*)(sm + OFF_BIAS);
    float* rsum    = (float*)(sm + OFF_RSUM);
    float* gates_s = (float*)(sm + OFF_GATES);

    const int tid = threadIdx.x;
    const int lane = tid & 31;
    const int wid = tid >> 5;
    const int m0 = blockIdx.x * 64;
    const __nv_bfloat16* Whi = (MODE == 0) ? g_Whi_e : g_Whi_n;
    const __nv_bfloat16* Wlo = (MODE == 0) ? g_Wlo_e : g_Wlo_n;

    bias_s[tid] = bih[tid] + bhh[tid];
    if (tid < 128) rsum[tid] = 0.f;

    // prologue: stage sub-chunk 0
    issue_B(smb, BBUF(0, 0), BBUF(0, 1), Whi, Wlo, KTOT, 0, tid);
    CP_COMMIT();
    {
        float4 p0[2];
        pf_A<MODE>(p0, 0, m0, Mrows, tid, feat, nfeat, grepr, h_in, srcI, dstI, rgraph);
        st_A(p0, sm, ABUF(0, 0), ABUF(0, 1), tid);
    }
    CP_WAIT0();
    __syncthreads();

    float acc[2][8][4];
    #pragma unroll
    for (int i = 0; i < 2; ++i)
        #pragma unroll
        for (int j = 0; j < 8; ++j)
            #pragma unroll
            for (int k = 0; k < 4; ++k) acc[i][j][k] = 0.f;

    const int wm = wid & 1, wn = wid >> 1;
    const uint32_t aoff = (uint32_t)((wm * 32 + (lane & 15)) * 80 + (lane >> 4) * 16);
    const uint32_t boff = (uint32_t)(wn * 5120 + (lane & 15) * 80 + (lane >> 4) * 16);

    #pragma unroll 1
    for (int c = 0; c < NC; ++c) {
        const int cur = c & 1, nxt = cur ^ 1;
        float4 pf[2];
        if (c + 1 < NC) {
            issue_B(smb, BBUF(nxt, 0), BBUF(nxt, 1), Whi, Wlo, KTOT, c + 1, tid);
            CP_COMMIT();
            pf_A<MODE>(pf, c + 1, m0, Mrows, tid, feat, nfeat, grepr, h_in, srcI, dstI, rgraph);
        }
        compute32(smb, ABUF(cur, 0), ABUF(cur, 1), BBUF(cur, 0), BBUF(cur, 1), aoff, boff, acc);
        if (c + 1 < NC) {
            st_A(pf, sm, ABUF(nxt, 0), ABUF(nxt, 1), tid);
            CP_WAIT0();
        }
        __syncthreads();
    }

    // ---- acc -> gates_s[64][260] (overlays A/B smem) ----
    #pragma unroll
    for (int mt = 0; mt < 2; ++mt) {
        int r0 = wm * 32 + mt * 16 + (lane >> 2);
        #pragma unroll
        for (int nt = 0; nt < 8; ++nt) {
            int nc = wn * 64 + nt * 8 + (lane & 3) * 2;
            *(float2*)&gates_s[r0 * 260 + nc]       = make_float2(acc[mt][nt][0], acc[mt][nt][1]);
            *(float2*)&gates_s[(r0 + 8) * 260 + nc] = make_float2(acc[mt][nt][2], acc[mt][nt][3]);
        }
    }
    __syncthreads();

    // ---- fused LSTM pointwise + mailbox scatter + per-graph sums ----
    const int d = tid & 63;
    const float bi = bias_s[d], bf = bias_s[64 + d], bg = bias_s[128 + d], bo = bias_s[192 + d];
    const int gfirst = rgraph[m0];
    int mlast = (m0 + 63 < Mrows) ? (m0 + 63) : (Mrows - 1);
    const int glast = rgraph[mlast];
    float a0 = 0.f, a1 = 0.f;
    #pragma unroll 4
    for (int it = 0; it < 16; ++it) {
        int ml = it * 4 + (tid >> 6);
        int grow = m0 + ml;
        if (grow < Mrows) {
            float gi = gates_s[ml * 260 + d] + bi;
            float gf = gates_s[ml * 260 + 64 + d] + bf;
            float gg = gates_s[ml * 260 + 128 + d] + bg;
            float go = gates_s[ml * 260 + 192 + d] + bo;
            float c2 = sigm(gf) * c_in[(size_t)grow * 64 + d] + sigm(gi) * tanh_(gg);
            float h = sigm(go) * tanh_(c2);
            float r = fmaxf(h, 0.f);
            out_r[(size_t)grow * 64 + d] = r;
            out_h[(size_t)grow * 64 + d] = h;
            out_c[(size_t)grow * 64 + d] = c2;
            if (MODE == 0) atomicAdd(&g_mail[(size_t)dstI[grow] * 64 + d], r);
            if (rgraph[grow] == gfirst) a0 += r; else a1 += r;
        }
    }
    atomicAdd(&rsum[d], a0);
    atomicAdd(&rsum[64 + d], a1);
    __syncthreads();
    float* comb = (MODE == 0) ? g_ecomb : g_ncomb;
    if (tid < 64) atomicAdd(&comb[(size_t)gfirst * 64 + tid], rsum[tid]);
    else if (tid < 128 && glast != gfirst)
        atomicAdd(&comb[(size_t)glast * 64 + (tid - 64)], rsum[tid]);
}

// ---------------- W pre-split (fp32 -> bf16 hi/lo, K-major concat) ----------------
__global__ void splitw_kernel(const float* __restrict__ Wih_e, const float* __restrict__ Whh_e,
                              const float* __restrict__ Wih_n, const float* __restrict__ Whh_n)
{
    int i = blockIdx.x * 256 + threadIdx.x;
    if (i < 256 * 320) {
        int g = i / 320, k = i - g * 320;
        float v = (k < 256) ? Wih_e[g * 256 + k] : Whh_e[g * 64 + (k - 256)];
        __nv_bfloat16 h = __float2bfloat16(v);
        g_Whi_e[i] = h;
        g_Wlo_e[i] = __float2bfloat16(v - __bfloat162float(h));
    }
    if (i < 256 * 256) {
        int g = i >> 8, k = i & 255;
        float v = (k < 192) ? Wih_n[g * 192 + k] : Whh_n[g * 64 + (k - 192)];
        __nv_bfloat16 h = __float2bfloat16(v);
        g_Whi_n[i] = h;
        g_Wlo_n[i] = __float2bfloat16(v - __bfloat162float(h));
    }
}

__global__ void zero_scratch_kernel()
{
    int i = blockIdx.x * 256 + threadIdx.x;
    if (i < NN_ * 64) g_mail[i] = 0.f;
    if (i < B_ * 64) { g_ecomb[i] = 0.f; g_ncomb[i] = 0.f; }
}

// ---------------- graph-level LSTM (B=50) ----------------
__global__ void graph_lstm_kernel(
    const float* __restrict__ grepr,
    const float* __restrict__ h_in,
    const float* __restrict__ c_in,
    const float* __restrict__ Wih,
    const float* __restrict__ Whh,
    const float* __restrict__ bih,
    const float* __restrict__ bhh,
    float* __restrict__ out_r,
    float* __restrict__ out_h,
    float* __restrict__ out_c)
{
    __shared__ float xu[256];
    __shared__ float gs[256];
    const int b = blockIdx.x;
    const int tid = threadIdx.x;

    if (tid < 64)       xu[tid] = g_ncomb[b * 64 + tid];
    else if (tid < 128) xu[tid] = g_ecomb[b * 64 + (tid - 64)];
    else if (tid < 192) xu[tid] = grepr[b * 64 + (tid - 128)];
    else                xu[tid] = h_in[b * 64 + (tid - 192)];
    __syncthreads();

    float a = bih[tid] + bhh[tid];
    const float* wih_row = Wih + (size_t)tid * 192;
    #pragma unroll 8
    for (int k4 = 0; k4 < 48; ++k4) {
        float4 w = *(const float4*)&wih_row[k4 * 4];
        a += w.x * xu[k4 * 4] + w.y * xu[k4 * 4 + 1] + w.z * xu[k4 * 4 + 2] + w.w * xu[k4 * 4 + 3];
    }
    const float* whh_row = Whh + (size_t)tid * 64;
    #pragma unroll 8
    for (int k4 = 0; k4 < 16; ++k4) {
        float4 w = *(const float4*)&whh_row[k4 * 4];
        a += w.x * xu[192 + k4 * 4] + w.y * xu[192 + k4 * 4 + 1]
           + w.z * xu[192 + k4 * 4 + 2] + w.w * xu[192 + k4 * 4 + 3];
    }
    gs[tid] = a;
    __syncthreads();

    if (tid < 64) {
        float gi = gs[tid], gf = gs[64 + tid], gg = gs[128 + tid], go = gs[192 + tid];
        float c2 = sigm(gf) * c_in[b * 64 + tid] + sigm(gi) * tanh_(gg);
        float h = sigm(go) * tanh_(c2);
        out_r[b * 64 + tid] = fmaxf(h, 0.f);
        out_h[b * 64 + tid] = h;
        out_c[b * 64 + tid] = c2;
    }
}

extern "C" void kernel_launch(void* const* d_in, const int* in_sizes, int n_in,
                              void* d_out, int out_size)
{
    const float* edge_feat  = (const float*)d_in[0];
    const float* node_feat  = (const float*)d_in[1];
    const float* g_repr     = (const float*)d_in[2];
    const float* edge_h     = (const float*)d_in[3];
    const float* edge_c     = (const float*)d_in[4];
    const float* node_h     = (const float*)d_in[5];
    const float* node_c     = (const float*)d_in[6];
    const float* graph_h    = (const float*)d_in[7];
    const float* graph_c    = (const float*)d_in[8];
    const float* Wih_e      = (const float*)d_in[9];
    const float* Whh_e      = (const float*)d_in[10];
    const float* bih_e      = (const float*)d_in[11];
    const float* bhh_e      = (const float*)d_in[12];
    const float* Wih_n      = (const float*)d_in[13];
    const float* Whh_n      = (const float*)d_in[14];
    const float* bih_n      = (const float*)d_in[15];
    const float* bhh_n      = (const float*)d_in[16];
    const float* Wih_u      = (const float*)d_in[17];
    const float* Whh_u      = (const float*)d_in[18];
    const float* bih_u      = (const float*)d_in[19];
    const float* bhh_u      = (const float*)d_in[20];
    const int*   src        = (const int*)d_in[21];
    const int*   dst        = (const int*)d_in[22];
    const int*   edge_graph = (const int*)d_in[23];
    const int*   node_graph = (const int*)d_in[24];

    float* out = (float*)d_out;
    const size_t ED = (size_t)E_ * 64;
    const size_t ND = (size_t)NN_ * 64;
    const size_t BD = (size_t)B_ * 64;
    float* e_out = out;
    float* h_e   = out + ED;
    float* c_e   = out + 2 * ED;
    float* n_out = out + 3 * ED;
    float* h_n   = n_out + ND;
    float* c_n   = n_out + 2 * ND;
    float* u_out = n_out + 3 * ND;
    float* h_u   = u_out + BD;
    float* c_u   = u_out + 2 * BD;

    cudaFuncSetAttribute(lstm_mma_kernel<0>, cudaFuncAttributeMaxDynamicSharedMemorySize, SMEM_SZ);
    cudaFuncSetAttribute(lstm_mma_kernel<1>, cudaFuncAttributeMaxDynamicSharedMemorySize, SMEM_SZ);

    // 1) W pre-split + scratch zero
    splitw_kernel<<<320, 256>>>(Wih_e, Whh_e, Wih_n, Whh_n);
    zero_scratch_kernel<<<(NN_ * 64 + 255) / 256, 256>>>();

    // 2) edge LSTM (mma.sync bf16 3-pass, 2 CTA/SM) + mailbox scatter + e_comb
    lstm_mma_kernel<0><<<E_ / 64, 256, SMEM_SZ>>>(
        edge_feat, node_feat, g_repr, edge_h, edge_c,
        bih_e, bhh_e, src, dst, edge_graph,
        e_out, h_e, c_e, E_);

    // 3) node LSTM (consumes mail) + n_comb
    lstm_mma_kernel<1><<<(NN_ + 63) / 64, 256, SMEM_SZ>>>(
        node_feat, nullptr, g_repr, node_h, node_c,
        bih_n, bhh_n, nullptr, nullptr, node_graph,
        n_out, h_n, c_n, NN_);

    // 4) graph LSTM
    graph_lstm_kernel<<<B_, 256>>>(
        g_repr, graph_h, graph_c,
        Wih_u, Whh_u, bih_u, bhh_u,
        u_out, h_u, c_u);
}

// round 6
// speedup vs baseline: 4.6489x; 1.0190x over previous
#include <cuda_runtime.h>
#include <cuda_bf16.h>
#include <math.h>
#include <stdint.h>

#define E_ 400000
#define NN_ 50000
#define B_ 50

// ---------------- device scratch (no allocs allowed) ----------------
__device__ float g_mail[NN_ * 64];
__device__ float g_ecomb[B_ * 64];
__device__ float g_ncomb[B_ * 64];
__device__ float g_gbias_e[B_ * 256];
__device__ float g_gbias_n[B_ * 256];
// pre-split weights, K-major concat (grepr segment removed)
__device__ __align__(16) __nv_bfloat16 g_Whi_e[256 * 256];
__device__ __align__(16) __nv_bfloat16 g_Wlo_e[256 * 256];
__device__ __align__(16) __nv_bfloat16 g_Whi_n[256 * 192];
__device__ __align__(16) __nv_bfloat16 g_Wlo_n[256 * 192];
// pre-split gathered operands
__device__ __align__(16) __nv_bfloat16 g_nf_hi[NN_ * 64];
__device__ __align__(16) __nv_bfloat16 g_nf_lo[NN_ * 64];
__device__ __align__(16) __nv_bfloat16 g_nh_hi[NN_ * 64];
__device__ __align__(16) __nv_bfloat16 g_nh_lo[NN_ * 64];
__device__ __align__(16) __nv_bfloat16 g_ml_hi[NN_ * 64];
__device__ __align__(16) __nv_bfloat16 g_ml_lo[NN_ * 64];

// ---------------- smem layout (bytes); rows padded to 144 B ----------------
#define OFF_BIAS 0                      // 256 f32
#define OFF_RSUM 1024                   // 128 f32
#define OFF_GB   1536                   // 2 x 256 f32 per-graph gate bias
#define OFF_A    3584                   // A[buf][hl]: 128*144 = 18432 each
#define ABUF(buf, hl) (OFF_A + ((buf) * 2 + (hl)) * 18432)
#define OFF_B    77312                  // B[buf][hl]: 256*144 = 36864 each
#define BBUF(buf, hl) (OFF_B + ((buf) * 2 + (hl)) * 36864)
#define SMEM_SZ  224768
#define OFF_GATES 3584                  // overlay after GEMM: 128 x 260 f32

// ---------------- PTX helpers (baseline sm_80-class only) ----------------
__device__ __forceinline__ uint32_t smem_u32(const void* p) {
    uint32_t a;
    asm("{ .reg .u64 t; cvta.to.shared.u64 t, %1; cvt.u32.u64 %0, t; }" : "=r"(a) : "l"(p));
    return a;
}
#define CP_ASYNC16(dst, src) \
    asm volatile("cp.async.ca.shared.global [%0], [%1], 16;" :: "r"(dst), "l"(src))
#define CP_COMMIT() asm volatile("cp.async.commit_group;" ::: "memory")
#define CP_WAIT0()  asm volatile("cp.async.wait_group 0;" ::: "memory")
#define CP_WAIT1()  asm volatile("cp.async.wait_group 1;" ::: "memory")

__device__ __forceinline__ void ldsm4(uint32_t* r, uint32_t a) {
    asm volatile("ldmatrix.sync.aligned.m8n8.x4.shared.b16 {%0,%1,%2,%3}, [%4];"
        : "=r"(r[0]), "=r"(r[1]), "=r"(r[2]), "=r"(r[3]) : "r"(a));
}
__device__ __forceinline__ void mma16816(float* d, const uint32_t* a, uint32_t b0, uint32_t b1) {
    asm volatile("mma.sync.aligned.m16n8k16.row.col.f32.bf16.bf16.f32 "
        "{%0,%1,%2,%3},{%4,%5,%6,%7},{%8,%9},{%0,%1,%2,%3};"
        : "+f"(d[0]), "+f"(d[1]), "+f"(d[2]), "+f"(d[3])
        : "r"(a[0]), "r"(a[1]), "r"(a[2]), "r"(a[3]), "r"(b0), "r"(b1));
}

// ---------------- math helpers ----------------
__device__ __forceinline__ float sigm(float x) { return 1.0f / (1.0f + __expf(-x)); }
__device__ __forceinline__ float tanh_(float x) {
    return __fdividef(2.0f, 1.0f + __expf(-2.0f * x)) - 1.0f;
}
__device__ __forceinline__ void split2(float a, float b, uint32_t& hi, uint32_t& lo) {
    __nv_bfloat16 h0 = __float2bfloat16(a), h1 = __float2bfloat16(b);
    float r0 = a - __bfloat162float(h0), r1 = b - __bfloat162float(h1);
    __nv_bfloat16 l0 = __float2bfloat16(r0), l1 = __float2bfloat16(r1);
    hi = ((uint32_t)__bfloat16_as_ushort(h1) << 16) | __bfloat16_as_ushort(h0);
    lo = ((uint32_t)__bfloat16_as_ushort(l1) << 16) | __bfloat16_as_ushort(l0);
}

// ---------------- staging ----------------
// pre-split bf16 A chunk via cp.async (4 cp/thread)
template <int MODE>
__device__ __forceinline__ void issue_A_cp(uint32_t smb, int oh, int ol,
    int c, int m0, int Mrows, int tid,
    const int* __restrict__ srcI, const int* __restrict__ dstI)
{
    #pragma unroll
    for (int t = 0; t < 2; ++t) {
        int idx = tid + t * 512;
        int rl = idx >> 3, u = idx & 7;
        int grow = m0 + rl;
        if (grow >= Mrows) grow = Mrows - 1;
        const __nv_bfloat16 *hi, *lo;
        int ridx;
        if (MODE == 0) {
            hi = g_nf_hi; lo = g_nf_lo;
            ridx = (c == 1) ? srcI[grow] : dstI[grow];
        } else {
            if (c == 0)      { hi = g_nf_hi; lo = g_nf_lo; ridx = grow; }
            else if (c == 1) { hi = g_ml_hi; lo = g_ml_lo; ridx = grow; }
            else             { hi = g_nh_hi; lo = g_nh_lo; ridx = grow; }
        }
        CP_ASYNC16(smb + oh + rl * 144 + u * 16,
                   (const char*)(hi + (size_t)ridx * 64) + u * 16);
        CP_ASYNC16(smb + ol + rl * 144 + u * 16,
                   (const char*)(lo + (size_t)ridx * 64) + u * 16);
    }
}

// own-row f32 chunk: LDG + split + STS (edge_feat / edge_h)
__device__ __forceinline__ void stage_f32(const float* __restrict__ base,
    char* sm, int oh, int ol, int m0, int Mrows, int tid)
{
    float4 pf[4];
    #pragma unroll
    for (int t = 0; t < 4; ++t) {
        int idx = tid + t * 512;
        int rl = idx >> 4, q = idx & 15;
        int grow = m0 + rl;
        pf[t] = make_float4(0.f, 0.f, 0.f, 0.f);
        if (grow < Mrows) pf[t] = *(const float4*)(base + (size_t)grow * 64 + q * 4);
    }
    #pragma unroll
    for (int t = 0; t < 4; ++t) {
        int idx = tid + t * 512;
        int rl = idx >> 4, q = idx & 15;
        uint32_t h01, l01, h23, l23;
        split2(pf[t].x, pf[t].y, h01, l01);
        split2(pf[t].z, pf[t].w, h23, l23);
        *(uint2*)(sm + oh + rl * 144 + q * 8) = make_uint2(h01, h23);
        *(uint2*)(sm + ol + rl * 144 + q * 8) = make_uint2(l01, l23);
    }
}

// B chunk (256 gates x 64 k, hi+lo) via cp.async (8 cp/thread)
__device__ __forceinline__ void issue_B(uint32_t smb, int oh, int ol,
    const __nv_bfloat16* __restrict__ Whi, const __nv_bfloat16* __restrict__ Wlo,
    int KTOT, int c, int tid)
{
    #pragma unroll
    for (int t = 0; t < 4; ++t) {
        int idx = tid + t * 512;
        int g = idx >> 3, s = idx & 7;
        CP_ASYNC16(smb + oh + g * 144 + s * 16,
                   (const char*)(Whi + (size_t)g * KTOT + c * 64 + s * 8));
    }
    #pragma unroll
    for (int t = 0; t < 4; ++t) {
        int idx = tid + t * 512;
        int g = idx >> 3, s = idx & 7;
        CP_ASYNC16(smb + ol + g * 144 + s * 16,
                   (const char*)(Wlo + (size_t)g * KTOT + c * 64 + s * 8));
    }
}

// merged 3-pass mma over one K=64 chunk; warp tile 32x64
__device__ __forceinline__ void compute64(uint32_t smb, int aHi, int aLo, int bHi, int bLo,
                                          uint32_t aoff, uint32_t boff, float (&acc)[2][8][4])
{
    #pragma unroll
    for (int kt = 0; kt < 4; ++kt) {
        uint32_t b4[4][4];
        #pragma unroll
        for (int g = 0; g < 4; ++g) ldsm4(b4[g], smb + bHi + boff + g * 2304 + kt * 32);
        #pragma unroll
        for (int mt = 0; mt < 2; ++mt) {
            uint32_t a[4];
            ldsm4(a, smb + aHi + aoff + mt * 2304 + kt * 32);
            #pragma unroll
            for (int g = 0; g < 4; ++g) {
                mma16816(acc[mt][2 * g],     a, b4[g][0], b4[g][2]);
                mma16816(acc[mt][2 * g + 1], a, b4[g][1], b4[g][3]);
            }
            ldsm4(a, smb + aLo + aoff + mt * 2304 + kt * 32);
            #pragma unroll
            for (int g = 0; g < 4; ++g) {
                mma16816(acc[mt][2 * g],     a, b4[g][0], b4[g][2]);
                mma16816(acc[mt][2 * g + 1], a, b4[g][1], b4[g][3]);
            }
        }
    }
    #pragma unroll
    for (int kt = 0; kt < 4; ++kt) {
        uint32_t b4[4][4];
        #pragma unroll
        for (int g = 0; g < 4; ++g) ldsm4(b4[g], smb + bLo + boff + g * 2304 + kt * 32);
        #pragma unroll
        for (int mt = 0; mt < 2; ++mt) {
            uint32_t a[4];
            ldsm4(a, smb + aHi + aoff + mt * 2304 + kt * 32);
            #pragma unroll
            for (int g = 0; g < 4; ++g) {
                mma16816(acc[mt][2 * g],     a, b4[g][0], b4[g][2]);
                mma16816(acc[mt][2 * g + 1], a, b4[g][1], b4[g][3]);
            }
        }
    }
}

// MODE 0: edge (K=256: feat | nf[src] | nf[dst] | h), MODE 1: node (K=192: nf | mail | nh)
template <int MODE>
__global__ void __launch_bounds__(512, 1)
lstm_mma_kernel(const float* __restrict__ feat,      // edge_feat (MODE 0 only)
                const float* __restrict__ h_f32,     // edge_h (MODE 0 only)
                const float* __restrict__ c_in,
                const float* __restrict__ bih,
                const float* __restrict__ bhh,
                const int* __restrict__ srcI,
                const int* __restrict__ dstI,
                const int* __restrict__ rgraph,
                float* __restrict__ out_r,
                float* __restrict__ out_h,
                float* __restrict__ out_c,
                int Mrows)
{
    constexpr int KTOT = (MODE == 0) ? 256 : 192;
    constexpr int NC = KTOT / 64;
    extern __shared__ char sm[];
    const uint32_t smb = smem_u32(sm);
    float* bias_s  = (float*)(sm + OFF_BIAS);
    float* rsum    = (float*)(sm + OFF_RSUM);
    float* gb_s    = (float*)(sm + OFF_GB);
    float* gates_s = (float*)(sm + OFF_GATES);

    const int tid = threadIdx.x;
    const int lane = tid & 31;
    const int wid = tid >> 5;
    const int m0 = blockIdx.x * 128;
    const __nv_bfloat16* Whi = (MODE == 0) ? g_Whi_e : g_Whi_n;
    const __nv_bfloat16* Wlo = (MODE == 0) ? g_Wlo_e : g_Wlo_n;
    const float* gbias = (MODE == 0) ? g_gbias_e : g_gbias_n;

    if (tid < 256) bias_s[tid] = bih[tid] + bhh[tid];
    if (tid < 128) rsum[tid] = 0.f;

    const int gfirst = rgraph[m0];
    int mlast = (m0 + 127 < Mrows) ? (m0 + 127) : (Mrows - 1);
    const int glast = rgraph[mlast];
    // stage per-graph gate bias (precomputed grepr @ Wseg)
    if (tid < 256) gb_s[tid] = gbias[(size_t)gfirst * 256 + tid];
    else           gb_s[tid] = gbias[(size_t)glast * 256 + (tid - 256)];

    // prologue: chunk 0
    if (MODE == 1)
        issue_A_cp<1>(smb, ABUF(0, 0), ABUF(0, 1), 0, m0, Mrows, tid, srcI, dstI);
    issue_B(smb, BBUF(0, 0), BBUF(0, 1), Whi, Wlo, KTOT, 0, tid);
    CP_COMMIT();
    if (MODE == 0)
        stage_f32(feat, sm, ABUF(0, 0), ABUF(0, 1), m0, Mrows, tid);

    float acc[2][8][4];
    #pragma unroll
    for (int i = 0; i < 2; ++i)
        #pragma unroll
        for (int j = 0; j < 8; ++j)
            #pragma unroll
            for (int k = 0; k < 4; ++k) acc[i][j][k] = 0.f;

    const int wm = wid & 3, wn = wid >> 2;
    const uint32_t aoff = (uint32_t)((wm * 32 + (lane & 15)) * 144 + (lane >> 4) * 16);
    const uint32_t boff = (uint32_t)((wn * 64 + (lane & 15)) * 144 + (lane >> 4) * 16);

    #pragma unroll 1
    for (int c = 0; c < NC; ++c) {
        const int nxt = (c + 1) & 1;
        const bool have_next = (c + 1 < NC);
        const bool next_f32 = have_next && (MODE == 0) && (c + 1 == NC - 1);
        if (have_next) {
            if (!next_f32)
                issue_A_cp<MODE>(smb, ABUF(nxt, 0), ABUF(nxt, 1), c + 1, m0, Mrows, tid, srcI, dstI);
            issue_B(smb, BBUF(nxt, 0), BBUF(nxt, 1), Whi, Wlo, KTOT, c + 1, tid);
            CP_COMMIT();
            if (next_f32)
                stage_f32(h_f32, sm, ABUF(nxt, 0), ABUF(nxt, 1), m0, Mrows, tid);
        }
        if (have_next) CP_WAIT1(); else CP_WAIT0();
        __syncthreads();
        compute64(smb, ABUF(c & 1, 0), ABUF(c & 1, 1), BBUF(c & 1, 0), BBUF(c & 1, 1),
                  aoff, boff, acc);
        __syncthreads();
    }

    // ---- acc -> gates_s[128][260] (overlays A/B smem) ----
    #pragma unroll
    for (int mt = 0; mt < 2; ++mt) {
        int r0 = wm * 32 + mt * 16 + (lane >> 2);
        #pragma unroll
        for (int nt = 0; nt < 8; ++nt) {
            int nc = wn * 64 + nt * 8 + (lane & 3) * 2;
            *(float2*)&gates_s[r0 * 260 + nc]       = make_float2(acc[mt][nt][0], acc[mt][nt][1]);
            *(float2*)&gates_s[(r0 + 8) * 260 + nc] = make_float2(acc[mt][nt][2], acc[mt][nt][3]);
        }
    }
    __syncthreads();

    // ---- fused LSTM pointwise + mailbox scatter + per-graph sums ----
    const int d = tid & 63;
    const int ms = tid >> 6;
    const float bi = bias_s[d], bf = bias_s[64 + d], bg = bias_s[128 + d], bo = bias_s[192 + d];
    float a0 = 0.f, a1 = 0.f;
    #pragma unroll 4
    for (int it = 0; it < 16; ++it) {
        int ml = it * 8 + ms;
        int grow = m0 + ml;
        if (grow < Mrows) {
            int sel = (rgraph[grow] == gfirst) ? 0 : 256;
            float gi = gates_s[ml * 260 + d]        + bi + gb_s[sel + d];
            float gf = gates_s[ml * 260 + 64 + d]   + bf + gb_s[sel + 64 + d];
            float gg = gates_s[ml * 260 + 128 + d]  + bg + gb_s[sel + 128 + d];
            float go = gates_s[ml * 260 + 192 + d]  + bo + gb_s[sel + 192 + d];
            float c2 = sigm(gf) * c_in[(size_t)grow * 64 + d] + sigm(gi) * tanh_(gg);
            float h = sigm(go) * tanh_(c2);
            float r = fmaxf(h, 0.f);
            out_r[(size_t)grow * 64 + d] = r;
            out_h[(size_t)grow * 64 + d] = h;
            out_c[(size_t)grow * 64 + d] = c2;
            if (MODE == 0) atomicAdd(&g_mail[(size_t)dstI[grow] * 64 + d], r);
            if (sel == 0) a0 += r; else a1 += r;
        }
    }
    atomicAdd(&rsum[d], a0);
    atomicAdd(&rsum[64 + d], a1);
    __syncthreads();
    float* comb = (MODE == 0) ? g_ecomb : g_ncomb;
    if (tid < 64) atomicAdd(&comb[(size_t)gfirst * 64 + tid], rsum[tid]);
    else if (tid < 128 && glast != gfirst)
        atomicAdd(&comb[(size_t)glast * 64 + (tid - 64)], rsum[tid]);
}

// ---------------- prep kernels ----------------
// W pre-split, K-major, grepr segment removed
__global__ void splitw_kernel(const float* __restrict__ Wih_e, const float* __restrict__ Whh_e,
                              const float* __restrict__ Wih_n, const float* __restrict__ Whh_n)
{
    int i = blockIdx.x * 256 + threadIdx.x;
    if (i < 256 * 256) {
        int g = i >> 8, k = i & 255;
        // edge: cols [0,192) of Wih_e (feat|nfsrc|nfdst), then Whh_e
        float v = (k < 192) ? Wih_e[g * 256 + k] : Whh_e[g * 64 + (k - 192)];
        __nv_bfloat16 h = __float2bfloat16(v);
        g_Whi_e[i] = h;
        g_Wlo_e[i] = __float2bfloat16(v - __bfloat162float(h));
    }
    if (i < 256 * 192) {
        int g = i / 192, k = i - g * 192;
        // node: cols [0,128) of Wih_n (feat|mail), then Whh_n
        float v = (k < 128) ? Wih_n[g * 192 + k] : Whh_n[g * 64 + (k - 128)];
        __nv_bfloat16 h = __float2bfloat16(v);
        g_Whi_n[i] = h;
        g_Wlo_n[i] = __float2bfloat16(v - __bfloat162float(h));
    }
}

// per-graph gate bias: gbias_e = grepr @ Wih_e[:,192:256].T ; gbias_n = grepr @ Wih_n[:,128:192].T
__global__ void gbias_kernel(const float* __restrict__ grepr,
                             const float* __restrict__ Wih_e,
                             const float* __restrict__ Wih_n)
{
    __shared__ float gsh[64];
    const int b = blockIdx.x, tid = threadIdx.x;
    if (tid < 64) gsh[tid] = grepr[b * 64 + tid];
    __syncthreads();
    float ae = 0.f, an = 0.f;
    #pragma unroll 8
    for (int k = 0; k < 64; ++k) {
        ae += gsh[k] * Wih_e[tid * 256 + 192 + k];
        an += gsh[k] * Wih_n[tid * 192 + 128 + k];
    }
    g_gbias_e[b * 256 + tid] = ae;
    g_gbias_n[b * 256 + tid] = an;
}

// split node-level f32 operands to bf16 hi/lo
__global__ void prep_split_kernel(const float* __restrict__ nf, const float* __restrict__ nh)
{
    int i = blockIdx.x * 256 + threadIdx.x;
    if (i < NN_ * 64) {
        float v = nf[i];
        __nv_bfloat16 h = __float2bfloat16(v);
        g_nf_hi[i] = h; g_nf_lo[i] = __float2bfloat16(v - __bfloat162float(h));
        v = nh[i];
        h = __float2bfloat16(v);
        g_nh_hi[i] = h; g_nh_lo[i] = __float2bfloat16(v - __bfloat162float(h));
    }
}

__global__ void split_mail_kernel()
{
    int i = blockIdx.x * 256 + threadIdx.x;
    if (i < NN_ * 64) {
        float v = g_mail[i];
        __nv_bfloat16 h = __float2bfloat16(v);
        g_ml_hi[i] = h; g_ml_lo[i] = __float2bfloat16(v - __bfloat162float(h));
    }
}

__global__ void zero_scratch_kernel()
{
    int i = blockIdx.x * 256 + threadIdx.x;
    if (i < NN_ * 64) g_mail[i] = 0.f;
    if (i < B_ * 64) { g_ecomb[i] = 0.f; g_ncomb[i] = 0.f; }
}

// ---------------- graph-level LSTM (B=50) ----------------
__global__ void graph_lstm_kernel(
    const float* __restrict__ grepr,
    const float* __restrict__ h_in,
    const float* __restrict__ c_in,
    const float* __restrict__ Wih,
    const float* __restrict__ Whh,
    const float* __restrict__ bih,
    const float* __restrict__ bhh,
    float* __restrict__ out_r,
    float* __restrict__ out_h,
    float* __restrict__ out_c)
{
    __shared__ float xu[256];
    __shared__ float gs[256];
    const int b = blockIdx.x;
    const int tid = threadIdx.x;

    if (tid < 64)       xu[tid] = g_ncomb[b * 64 + tid];
    else if (tid < 128) xu[tid] = g_ecomb[b * 64 + (tid - 64)];
    else if (tid < 192) xu[tid] = grepr[b * 64 + (tid - 128)];
    else                xu[tid] = h_in[b * 64 + (tid - 192)];
    __syncthreads();

    float a = bih[tid] + bhh[tid];
    const float* wih_row = Wih + (size_t)tid * 192;
    #pragma unroll 8
    for (int k4 = 0; k4 < 48; ++k4) {
        float4 w = *(const float4*)&wih_row[k4 * 4];
        a += w.x * xu[k4 * 4] + w.y * xu[k4 * 4 + 1] + w.z * xu[k4 * 4 + 2] + w.w * xu[k4 * 4 + 3];
    }
    const float* whh_row = Whh + (size_t)tid * 64;
    #pragma unroll 8
    for (int k4 = 0; k4 < 16; ++k4) {
        float4 w = *(const float4*)&whh_row[k4 * 4];
        a += w.x * xu[192 + k4 * 4] + w.y * xu[192 + k4 * 4 + 1]
           + w.z * xu[192 + k4 * 4 + 2] + w.w * xu[192 + k4 * 4 + 3];
    }
    gs[tid] = a;
    __syncthreads();

    if (tid < 64) {
        float gi = gs[tid], gf = gs[64 + tid], gg = gs[128 + tid], go = gs[192 + tid];
        float c2 = sigm(gf) * c_in[b * 64 + tid] + sigm(gi) * tanh_(gg);
        float h = sigm(go) * tanh_(c2);
        out_r[b * 64 + tid] = fmaxf(h, 0.f);
        out_h[b * 64 + tid] = h;
        out_c[b * 64 + tid] = c2;
    }
}

extern "C" void kernel_launch(void* const* d_in, const int* in_sizes, int n_in,
                              void* d_out, int out_size)
{
    const float* edge_feat  = (const float*)d_in[0];
    const float* node_feat  = (const float*)d_in[1];
    const float* g_repr     = (const float*)d_in[2];
    const float* edge_h     = (const float*)d_in[3];
    const float* edge_c     = (const float*)d_in[4];
    const float* node_h     = (const float*)d_in[5];
    const float* node_c     = (const float*)d_in[6];
    const float* graph_h    = (const float*)d_in[7];
    const float* graph_c    = (const float*)d_in[8];
    const float* Wih_e      = (const float*)d_in[9];
    const float* Whh_e      = (const float*)d_in[10];
    const float* bih_e      = (const float*)d_in[11];
    const float* bhh_e      = (const float*)d_in[12];
    const float* Wih_n      = (const float*)d_in[13];
    const float* Whh_n      = (const float*)d_in[14];
    const float* bih_n      = (const float*)d_in[15];
    const float* bhh_n      = (const float*)d_in[16];
    const float* Wih_u      = (const float*)d_in[17];
    const float* Whh_u      = (const float*)d_in[18];
    const float* bih_u      = (const float*)d_in[19];
    const float* bhh_u      = (const float*)d_in[20];
    const int*   src        = (const int*)d_in[21];
    const int*   dst        = (const int*)d_in[22];
    const int*   edge_graph = (const int*)d_in[23];
    const int*   node_graph = (const int*)d_in[24];

    float* out = (float*)d_out;
    const size_t ED = (size_t)E_ * 64;
    const size_t ND = (size_t)NN_ * 64;
    const size_t BD = (size_t)B_ * 64;
    float* e_out = out;
    float* h_e   = out + ED;
    float* c_e   = out + 2 * ED;
    float* n_out = out + 3 * ED;
    float* h_n   = n_out + ND;
    float* c_n   = n_out + 2 * ND;
    float* u_out = n_out + 3 * ND;
    float* h_u   = u_out + BD;
    float* c_u   = u_out + 2 * BD;

    cudaFuncSetAttribute(lstm_mma_kernel<0>, cudaFuncAttributeMaxDynamicSharedMemorySize, SMEM_SZ);
    cudaFuncSetAttribute(lstm_mma_kernel<1>, cudaFuncAttributeMaxDynamicSharedMemorySize, SMEM_SZ);

    // 1) prep: weight split, per-graph gate bias, operand pre-split, scratch zero
    splitw_kernel<<<256, 256>>>(Wih_e, Whh_e, Wih_n, Whh_n);
    gbias_kernel<<<B_, 256>>>(g_repr, Wih_e, Wih_n);
    prep_split_kernel<<<(NN_ * 64 + 255) / 256, 256>>>(node_feat, node_h);
    zero_scratch_kernel<<<(NN_ * 64 + 255) / 256, 256>>>();

    // 2) edge LSTM (K=256, M-tile 128, 512 thr) + mailbox scatter + e_comb
    lstm_mma_kernel<0><<<E_ / 128, 512, SMEM_SZ>>>(
        edge_feat, edge_h, edge_c, bih_e, bhh_e,
        src, dst, edge_graph, e_out, h_e, c_e, E_);

    // 3) split mail, then node LSTM (K=192, all cp.async) + n_comb
    split_mail_kernel<<<(NN_ * 64 + 255) / 256, 256>>>();
    lstm_mma_kernel<1><<<(NN_ + 127) / 128, 512, SMEM_SZ>>>(
        nullptr, nullptr, node_c, bih_n, bhh_n,
        nullptr, nullptr, node_graph, n_out, h_n, c_n, NN_);

    // 4) graph LSTM
    graph_lstm_kernel<<<B_, 256>>>(
        g_repr, graph_h, graph_c,
        Wih_u, Whh_u, bih_u, bhh_u,
        u_out, h_u, c_u);
}